// round 2
// baseline (speedup 1.0000x reference)
#include <cuda_runtime.h>
#include <math.h>

#define NN 1024
#define BB 4
#define TT 24
#define FF 96
#define KK 96            // T*B channels
#define RR (NN*KK)       // 98304 rows (== B*T*N)
#define EE 8192

// ---------------- scratch (device globals; no allocs allowed) ----------------
__device__ float g_h[RR*96];        // h (spatial GATs, reused) / hg (temporal)
__device__ float g_el[RR*4];
__device__ float g_er[RR*4];
__device__ float g_spatial[RR*96];  // (B,T,N,F) residual + x_attn
__device__ float g_temporal[RR*96]; // (B,T,N,F)
__device__ float g_attnT[BB*TT*TT];

// ---------------- fused 96x96 GEMM + el/er epilogue ----------------
// mode 0 (spatial): row = n*96 + k, k = t*B+b, x = input + spatial_emb
// mode 1 (temporal): row = (b*N+n)*24 + t, x = input
template<int HEADS>
__global__ void gemm96_fused(const float* __restrict__ A, const float* __restrict__ Badd,
                             const float* __restrict__ W, const float* __restrict__ al,
                             const float* __restrict__ ar, int mode, int rgpb)
{
    __shared__ float4 Ws[96*24];
    __shared__ float als[96], ars[96];
    __shared__ float4 xs4[4][24];
    __shared__ float redl[4][24], redr[4][24];
    int tid = threadIdx.x;                      // 96 threads
    const float4* W4 = reinterpret_cast<const float4*>(W);
    for (int i = tid; i < 96*24; i += 96) Ws[i] = W4[i];
    als[tid] = al[tid]; ars[tid] = ar[tid];
    __syncthreads();
    int c = tid % 24, rg = tid / 24;
    const float* xs = reinterpret_cast<const float*>(xs4[rg]);
    for (int it = 0; it < rgpb; ++it) {
        int row = (blockIdx.x * rgpb + it) * 4 + rg;
        int off;
        if (mode == 0) {
            int n = row / 96, k = row % 96;
            int b = k & 3, t = k >> 2;
            off = ((b*TT + t)*NN + n)*FF;
        } else {
            int r = row / 24, t = row % 24;
            int b = r >> 10, n = r & 1023;
            off = ((b*TT + t)*NN + n)*FF;
        }
        float4 xv = reinterpret_cast<const float4*>(A + off)[c];
        if (mode == 0) {
            float4 e = reinterpret_cast<const float4*>(Badd + off)[c];
            xv.x += e.x; xv.y += e.y; xv.z += e.z; xv.w += e.w;
        }
        xs4[rg][c] = xv;
        __syncthreads();
        float4 acc = make_float4(0.f,0.f,0.f,0.f);
        #pragma unroll
        for (int k = 0; k < 96; ++k) {
            float x = xs[k];
            float4 w = Ws[k*24 + c];
            acc.x = fmaf(x, w.x, acc.x);
            acc.y = fmaf(x, w.y, acc.y);
            acc.z = fmaf(x, w.z, acc.z);
            acc.w = fmaf(x, w.w, acc.w);
        }
        reinterpret_cast<float4*>(g_h + row*96)[c] = acc;
        int j0 = c*4;
        redl[rg][c] = acc.x*als[j0] + acc.y*als[j0+1] + acc.z*als[j0+2] + acc.w*als[j0+3];
        redr[rg][c] = acc.x*ars[j0] + acc.y*ars[j0+1] + acc.z*ars[j0+2] + acc.w*ars[j0+3];
        __syncthreads();
        if (c < HEADS) {
            const int per = 24 / HEADS;    // 8 (H=3,HD=32) or 6 (GH=4,GHD=24)
            float sl = 0.f, sr = 0.f;
            #pragma unroll
            for (int q = 0; q < per; ++q) { sl += redl[rg][c*per+q]; sr += redr[rg][c*per+q]; }
            g_el[row*HEADS + c] = sl;
            g_er[row*HEADS + c] = sr;
        }
        __syncthreads();
    }
}

// ---------------- GAT edge softmax + aggregation ----------------
// dst = arange(E) % N -> node n's 8 edges are e = n + j*1024, j in [0,8).
// One warp per (n,k); lane = d (HD=32); loop over H=3 heads.
__global__ void gat_agg(const int* __restrict__ src, const float* __restrict__ bias,
                        const float* __restrict__ inp, int gat)
{
    int gw = blockIdx.x * 4 + (threadIdx.x >> 5);
    int lane = threadIdx.x & 31;
    int n = gw / 96, k = gw % 96;
    int srcj = 0;
    if (lane < 8) srcj = src[n + lane*NN];
    float val = 0.f;
    #pragma unroll
    for (int hh = 0; hh < 3; ++hh) {
        float myer = g_er[(n*96 + k)*3 + hh];
        float e = -1e30f;
        if (lane < 8) {
            float x = g_el[(srcj*96 + k)*3 + hh] + myer;
            e = (x >= 0.f) ? x : 0.2f*x;           // leaky_relu 0.2
        }
        float m = e;
        m = fmaxf(m, __shfl_down_sync(0xffffffffu, m, 4));
        m = fmaxf(m, __shfl_down_sync(0xffffffffu, m, 2));
        m = fmaxf(m, __shfl_down_sync(0xffffffffu, m, 1));
        m = __shfl_sync(0xffffffffu, m, 0);        // segment max (always finite: 8 vals)
        float ex = (lane < 8) ? expf(e - m) : 0.f;
        float s = ex;
        s += __shfl_down_sync(0xffffffffu, s, 4);
        s += __shfl_down_sync(0xffffffffu, s, 2);
        s += __shfl_down_sync(0xffffffffu, s, 1);
        s = __shfl_sync(0xffffffffu, s, 0);
        float inv = 1.f / (s + 1e-9f);
        float acc = 0.f;
        #pragma unroll
        for (int j = 0; j < 8; ++j) {
            float aj = __shfl_sync(0xffffffffu, ex, j) * inv;
            int   sj = __shfl_sync(0xffffffffu, srcj, j);
            acc = fmaf(aj, g_h[(sj*96 + k)*96 + hh*32 + lane], acc);
        }
        val += acc + bias[hh*32 + lane];
    }
    val *= (1.f/3.f);                               // mean over heads
    int b2 = k / 24, t2 = k % 24;                   // reference's reshape scramble
    int o = ((b2*TT + t2)*NN + n)*FF + gat*32 + lane;
    g_spatial[o] = inp[o] + val;                    // residual_s + x_attn
}

// ---------------- attn_S = softmax(cov0 @ cov0^T, axis=2) ----------------
__global__ void attnS_gemm(const float* __restrict__ spatE, float* __restrict__ Sout)
{
    __shared__ float At[32][97];
    __shared__ float Bt[32][97];
    int b = blockIdx.z;
    int i0 = blockIdx.y * 32, j0 = blockIdx.x * 32;
    int tx = threadIdx.x, ty = threadIdx.y;
    const float* cov = spatE + (size_t)b*TT*NN*FF;  // t = 0 slice
    #pragma unroll
    for (int q = 0; q < 3; ++q) {
        At[ty][tx + q*32] = cov[(i0+ty)*96 + tx + q*32];
        Bt[ty][tx + q*32] = cov[(j0+ty)*96 + tx + q*32];
    }
    __syncthreads();
    float acc = 0.f;
    #pragma unroll
    for (int f = 0; f < 96; ++f) acc = fmaf(At[ty][f], Bt[tx][f], acc);
    Sout[((size_t)b*NN + i0 + ty)*NN + j0 + tx] = acc;
}

__global__ void rowsoftmax1024(float* __restrict__ S)
{
    int row = blockIdx.x;
    float* p = S + (size_t)row * 1024;
    int tid = threadIdx.x;   // 256
    float v[4];
    float m = -1e30f;
    #pragma unroll
    for (int q = 0; q < 4; ++q) { v[q] = p[tid + q*256]; m = fmaxf(m, v[q]); }
    __shared__ float red[8];
    __shared__ float red2[8];
    for (int o = 16; o >= 1; o >>= 1) m = fmaxf(m, __shfl_xor_sync(0xffffffffu, m, o));
    if ((tid & 31) == 0) red[tid >> 5] = m;
    __syncthreads();
    float mm = red[0];
    #pragma unroll
    for (int w = 1; w < 8; ++w) mm = fmaxf(mm, red[w]);
    float s = 0.f;
    #pragma unroll
    for (int q = 0; q < 4; ++q) { v[q] = expf(v[q] - mm); s += v[q]; }
    for (int o = 16; o >= 1; o >>= 1) s += __shfl_xor_sync(0xffffffffu, s, o);
    if ((tid & 31) == 0) red2[tid >> 5] = s;
    __syncthreads();
    float ss = 0.f;
    #pragma unroll
    for (int w = 0; w < 8; ++w) ss += red2[w];
    float inv = 1.f / ss;
    #pragma unroll
    for (int q = 0; q < 4; ++q) p[tid + q*256] = v[q] * inv;
}

// ---------------- attn_T = softmax(covT @ covT^T, axis=1) (column softmax!) --
__global__ void attnT_kernel(const float* __restrict__ tempE)
{
    __shared__ float cov[24][96];
    __shared__ float s[24][25];
    __shared__ float colmax[24], colsum[24];
    int b = blockIdx.x;
    int j = threadIdx.x, i = threadIdx.y;
    int tid = i*24 + j;
    for (int q = tid; q < 2304; q += 576) {
        int t = q / 96, f = q % 96;
        cov[t][f] = tempE[((b*TT + t)*NN)*FF + f];   // n = 0 slice
    }
    __syncthreads();
    float acc = 0.f;
    #pragma unroll
    for (int f = 0; f < 96; ++f) acc = fmaf(cov[i][f], cov[j][f], acc);
    s[i][j] = acc;
    __syncthreads();
    if (i == 0) {
        float m = -1e30f;
        for (int t = 0; t < 24; ++t) m = fmaxf(m, s[t][j]);
        colmax[j] = m;
    }
    __syncthreads();
    float e = expf(acc - colmax[j]);
    s[i][j] = e;
    __syncthreads();
    if (i == 0) {
        float sm = 0.f;
        for (int t = 0; t < 24; ++t) sm += s[t][j];
        colsum[j] = sm;
    }
    __syncthreads();
    g_attnT[(b*TT + i)*TT + j] = e / colsum[j];
}

// ---------------- temporal branch: per (b,n), all in smem ----------------
__global__ void temporal_kernel(const float* __restrict__ input)
{
    __shared__ float hgs[2304];
    __shared__ float xts[2304];
    __shared__ float xgs[2304];
    __shared__ float alph[2304];
    __shared__ float ats[576];
    __shared__ float elgs[96], ergs[96];
    int r = blockIdx.x;              // r = b*N + n
    int b = r >> 10, n = r & 1023;
    int tid = threadIdx.x;           // 256
    for (int q = tid; q < 2304; q += 256) hgs[q] = g_h[r*2304 + q];
    for (int q = tid; q < 2304; q += 256) {
        int t = q / 96, f = q % 96;
        xts[q] = input[((b*TT + t)*NN + n)*FF + f];
    }
    if (tid < 96) { elgs[tid] = g_el[r*96 + tid]; ergs[tid] = g_er[r*96 + tid]; }
    for (int q = tid; q < 576; q += 256) ats[q] = g_attnT[(n & 3)*576 + q]; // idx = r%B = n%4
    __syncthreads();
    if (tid < 96) {                  // softmax over j for (i,g)
        int i = tid >> 2, g = tid & 3;
        float eli = elgs[i*4 + g];
        float ev[24];
        float m = -1e30f;
        #pragma unroll
        for (int j = 0; j < 24; ++j) {
            float x = eli + ergs[j*4 + g];
            x = (x >= 0.f) ? x : 0.2f*x;
            ev[j] = x;
            m = fmaxf(m, x);
        }
        float s = 0.f;
        #pragma unroll
        for (int j = 0; j < 24; ++j) { ev[j] = expf(ev[j] - m); s += ev[j]; }
        float inv = 1.f / s;
        #pragma unroll
        for (int j = 0; j < 24; ++j) alph[tid*24 + j] = ev[j]*inv;
    }
    __syncthreads();
    for (int q = tid; q < 2304; q += 256) {   // xg = alpha @ hg
        int i = q / 96, rem = q % 96, g = rem / 24, d = rem % 24;
        float acc = 0.f;
        #pragma unroll
        for (int j = 0; j < 24; ++j)
            acc = fmaf(alph[(i*4+g)*24 + j], hgs[j*96 + g*24 + d], acc);
        xgs[q] = acc;
    }
    __syncthreads();
    for (int q = tid; q < 2304; q += 256) {   // emb gate + residual
        int i = q / 96, f = q % 96;
        float emb = 0.f;
        #pragma unroll
        for (int j = 0; j < 24; ++j) emb = fmaf(ats[i*24 + j], xts[j*96 + f], emb);
        float sg = 1.f / (1.f + expf(-emb));
        g_temporal[((b*TT + i)*NN + n)*FF + f] = xts[q] + xgs[q]*sg;
    }
}

// ---------------- fusion: z = sigmoid([sp,tp] @ Wf + bf); out = z*sp+(1-z)*tp+in
__global__ void fusion_kernel(const float* __restrict__ input, const float* __restrict__ Wf,
                              const float* __restrict__ bf, float* __restrict__ outp, int rgpb)
{
    extern __shared__ float4 Wfs[];            // 192*24 float4 = 73728 B
    __shared__ float4 sps4[4][24], tps4[4][24];
    __shared__ float bfs[96];
    int tid = threadIdx.x;                     // 96
    const float4* Wf4 = reinterpret_cast<const float4*>(Wf);
    for (int i = tid; i < 192*24; i += 96) Wfs[i] = Wf4[i];
    bfs[tid] = bf[tid];
    __syncthreads();
    int c = tid % 24, rg = tid / 24;
    const float* sps = reinterpret_cast<const float*>(sps4[rg]);
    const float* tps = reinterpret_cast<const float*>(tps4[rg]);
    for (int it = 0; it < rgpb; ++it) {
        int row = (blockIdx.x * rgpb + it) * 4 + rg;
        float4 s4 = reinterpret_cast<const float4*>(g_spatial + row*96)[c];
        float4 t4 = reinterpret_cast<const float4*>(g_temporal + row*96)[c];
        sps4[rg][c] = s4; tps4[rg][c] = t4;
        __syncthreads();
        int j0 = c*4;
        float4 acc = make_float4(bfs[j0], bfs[j0+1], bfs[j0+2], bfs[j0+3]);
        #pragma unroll
        for (int k = 0; k < 96; ++k) {
            float x = sps[k];
            float4 w = Wfs[k*24 + c];
            acc.x = fmaf(x, w.x, acc.x); acc.y = fmaf(x, w.y, acc.y);
            acc.z = fmaf(x, w.z, acc.z); acc.w = fmaf(x, w.w, acc.w);
        }
        #pragma unroll
        for (int k = 0; k < 96; ++k) {
            float x = tps[k];
            float4 w = Wfs[(96+k)*24 + c];
            acc.x = fmaf(x, w.x, acc.x); acc.y = fmaf(x, w.y, acc.y);
            acc.z = fmaf(x, w.z, acc.z); acc.w = fmaf(x, w.w, acc.w);
        }
        float4 z;
        z.x = 1.f/(1.f+expf(-acc.x)); z.y = 1.f/(1.f+expf(-acc.y));
        z.z = 1.f/(1.f+expf(-acc.z)); z.w = 1.f/(1.f+expf(-acc.w));
        float4 in4 = reinterpret_cast<const float4*>(input + row*96)[c];
        float4 o;
        o.x = z.x*s4.x + (1.f-z.x)*t4.x + in4.x;
        o.y = z.y*s4.y + (1.f-z.y)*t4.y + in4.y;
        o.z = z.z*s4.z + (1.f-z.z)*t4.z + in4.z;
        o.w = z.w*s4.w + (1.f-z.w)*t4.w + in4.w;
        reinterpret_cast<float4*>(outp + (size_t)row*96)[c] = o;
        __syncthreads();
    }
}

extern "C" void kernel_launch(void* const* d_in, const int* in_sizes, int n_in,
                              void* d_out, int out_size)
{
    const float* input = (const float*)d_in[0];
    const float* spatE = (const float*)d_in[1];
    const float* tempE = (const float*)d_in[2];
    const int*   srcs[3] = { (const int*)d_in[3], (const int*)d_in[5], (const int*)d_in[7] };
    const float* Ws_[3]  = { (const float*)d_in[9],  (const float*)d_in[13], (const float*)d_in[17] };
    const float* als_[3] = { (const float*)d_in[10], (const float*)d_in[14], (const float*)d_in[18] };
    const float* ars_[3] = { (const float*)d_in[11], (const float*)d_in[15], (const float*)d_in[19] };
    const float* bs_[3]  = { (const float*)d_in[12], (const float*)d_in[16], (const float*)d_in[20] };
    const float* Wg  = (const float*)d_in[21];
    const float* agl = (const float*)d_in[22];
    const float* agr = (const float*)d_in[23];
    const float* Wf  = (const float*)d_in[24];
    const float* bf  = (const float*)d_in[25];
    float* out   = (float*)d_out;
    float* attnS = out + (size_t)RR*96;   // out (B,T,N,F) then attn_S (B,N,N)

    // spatial GATs (sequential: g_h/g_el/g_er are reused)
    for (int g = 0; g < 3; ++g) {
        gemm96_fused<3><<<1024, 96>>>(input, spatE, Ws_[g], als_[g], ars_[g], 0, 24);
        gat_agg<<<RR/4, 128>>>(srcs[g], bs_[g], input, g);
    }
    // temporal projection (reuses g_h as hg, g_el/g_er as elg/erg)
    gemm96_fused<4><<<1024, 96>>>(input, input, Wg, agl, agr, 1, 24);

    // attn_S (second output): scores then in-place row softmax
    attnS_gemm<<<dim3(32,32,4), dim3(32,32)>>>(spatE, attnS);
    rowsoftmax1024<<<4096, 256>>>(attnS);

    // attn_T (tiny, column softmax)
    attnT_kernel<<<4, dim3(24,24)>>>(tempE);

    // temporal branch
    temporal_kernel<<<4096, 256>>>(input);

    // fusion
    cudaFuncSetAttribute(fusion_kernel, cudaFuncAttributeMaxDynamicSharedMemorySize, 73728);
    fusion_kernel<<<1024, 96, 73728>>>(input, Wf, bf, out, 24);
}

// round 3
// speedup vs baseline: 1.0007x; 1.0007x over previous
#include <cuda_runtime.h>
#include <math.h>

#define NN 1024
#define BB 4
#define TT 24
#define FF 96
#define KK 96            // T*B channels
#define RR (NN*KK)       // 98304 rows (== B*T*N)
#define EE 8192

// ---------------- scratch (device globals; no allocs allowed) ----------------
__device__ float g_h[RR*96];        // h (spatial GATs, reused) / hg (temporal)
__device__ float g_el[RR*4];
__device__ float g_er[RR*4];
__device__ float g_spatial[RR*96];  // (B,T,N,F) residual + x_attn
__device__ float g_temporal[RR*96]; // (B,T,N,F)
__device__ float g_attnT[BB*TT*TT];

// ---------------- fused 96x96 GEMM + el/er epilogue ----------------
// mode 0 (spatial): row = n*96 + k, k = t*B+b, x = input + spatial_emb
// mode 1 (temporal): row = (b*N+n)*24 + t, x = input
template<int HEADS>
__global__ void gemm96_fused(const float* __restrict__ A, const float* __restrict__ Badd,
                             const float* __restrict__ W, const float* __restrict__ al,
                             const float* __restrict__ ar, int mode, int rgpb)
{
    __shared__ float4 Ws[96*24];
    __shared__ float als[96], ars[96];
    __shared__ float4 xs4[4][24];
    __shared__ float redl[4][24], redr[4][24];
    int tid = threadIdx.x;                      // 96 threads
    const float4* W4 = reinterpret_cast<const float4*>(W);
    for (int i = tid; i < 96*24; i += 96) Ws[i] = W4[i];
    als[tid] = al[tid]; ars[tid] = ar[tid];
    __syncthreads();
    int c = tid % 24, rg = tid / 24;
    const float* xs = reinterpret_cast<const float*>(xs4[rg]);
    for (int it = 0; it < rgpb; ++it) {
        int row = (blockIdx.x * rgpb + it) * 4 + rg;
        int off;
        if (mode == 0) {
            int n = row / 96, k = row % 96;
            int b = k & 3, t = k >> 2;
            off = ((b*TT + t)*NN + n)*FF;
        } else {
            int r = row / 24, t = row % 24;
            int b = r >> 10, n = r & 1023;
            off = ((b*TT + t)*NN + n)*FF;
        }
        float4 xv = reinterpret_cast<const float4*>(A + off)[c];
        if (mode == 0) {
            float4 e = reinterpret_cast<const float4*>(Badd + off)[c];
            xv.x += e.x; xv.y += e.y; xv.z += e.z; xv.w += e.w;
        }
        xs4[rg][c] = xv;
        __syncthreads();
        float4 acc = make_float4(0.f,0.f,0.f,0.f);
        #pragma unroll
        for (int k = 0; k < 96; ++k) {
            float x = xs[k];
            float4 w = Ws[k*24 + c];
            acc.x = fmaf(x, w.x, acc.x);
            acc.y = fmaf(x, w.y, acc.y);
            acc.z = fmaf(x, w.z, acc.z);
            acc.w = fmaf(x, w.w, acc.w);
        }
        reinterpret_cast<float4*>(g_h + row*96)[c] = acc;
        int j0 = c*4;
        redl[rg][c] = acc.x*als[j0] + acc.y*als[j0+1] + acc.z*als[j0+2] + acc.w*als[j0+3];
        redr[rg][c] = acc.x*ars[j0] + acc.y*ars[j0+1] + acc.z*ars[j0+2] + acc.w*ars[j0+3];
        __syncthreads();
        if (c < HEADS) {
            const int per = 24 / HEADS;    // 8 (H=3,HD=32) or 6 (GH=4,GHD=24)
            float sl = 0.f, sr = 0.f;
            #pragma unroll
            for (int q = 0; q < per; ++q) { sl += redl[rg][c*per+q]; sr += redr[rg][c*per+q]; }
            g_el[row*HEADS + c] = sl;
            g_er[row*HEADS + c] = sr;
        }
        __syncthreads();
    }
}

// ---------------- GAT edge softmax + aggregation ----------------
// dst = arange(E) % N -> node n's 8 edges are e = n + j*1024, j in [0,8).
// One warp per (n,k); lane = d (HD=32); loop over H=3 heads.
__global__ void gat_agg(const int* __restrict__ src, const float* __restrict__ bias,
                        const float* __restrict__ inp, int gat)
{
    int gw = blockIdx.x * 4 + (threadIdx.x >> 5);
    int lane = threadIdx.x & 31;
    int n = gw / 96, k = gw % 96;
    int srcj = 0;
    if (lane < 8) srcj = src[n + lane*NN];
    float val = 0.f;
    #pragma unroll
    for (int hh = 0; hh < 3; ++hh) {
        float myer = g_er[(n*96 + k)*3 + hh];
        float e = -1e30f;
        if (lane < 8) {
            float x = g_el[(srcj*96 + k)*3 + hh] + myer;
            e = (x >= 0.f) ? x : 0.2f*x;           // leaky_relu 0.2
        }
        float m = e;
        m = fmaxf(m, __shfl_down_sync(0xffffffffu, m, 4));
        m = fmaxf(m, __shfl_down_sync(0xffffffffu, m, 2));
        m = fmaxf(m, __shfl_down_sync(0xffffffffu, m, 1));
        m = __shfl_sync(0xffffffffu, m, 0);        // segment max (always finite: 8 vals)
        float ex = (lane < 8) ? expf(e - m) : 0.f;
        float s = ex;
        s += __shfl_down_sync(0xffffffffu, s, 4);
        s += __shfl_down_sync(0xffffffffu, s, 2);
        s += __shfl_down_sync(0xffffffffu, s, 1);
        s = __shfl_sync(0xffffffffu, s, 0);
        float inv = 1.f / (s + 1e-9f);
        float acc = 0.f;
        #pragma unroll
        for (int j = 0; j < 8; ++j) {
            float aj = __shfl_sync(0xffffffffu, ex, j) * inv;
            int   sj = __shfl_sync(0xffffffffu, srcj, j);
            acc = fmaf(aj, g_h[(sj*96 + k)*96 + hh*32 + lane], acc);
        }
        val += acc + bias[hh*32 + lane];
    }
    val *= (1.f/3.f);                               // mean over heads
    int b2 = k / 24, t2 = k % 24;                   // reference's reshape scramble
    int o = ((b2*TT + t2)*NN + n)*FF + gat*32 + lane;
    g_spatial[o] = inp[o] + val;                    // residual_s + x_attn
}

// ---------------- attn_S = softmax(cov0 @ cov0^T, axis=2) ----------------
__global__ void attnS_gemm(const float* __restrict__ spatE, float* __restrict__ Sout)
{
    __shared__ float At[32][97];
    __shared__ float Bt[32][97];
    int b = blockIdx.z;
    int i0 = blockIdx.y * 32, j0 = blockIdx.x * 32;
    int tx = threadIdx.x, ty = threadIdx.y;
    const float* cov = spatE + (size_t)b*TT*NN*FF;  // t = 0 slice
    #pragma unroll
    for (int q = 0; q < 3; ++q) {
        At[ty][tx + q*32] = cov[(i0+ty)*96 + tx + q*32];
        Bt[ty][tx + q*32] = cov[(j0+ty)*96 + tx + q*32];
    }
    __syncthreads();
    float acc = 0.f;
    #pragma unroll
    for (int f = 0; f < 96; ++f) acc = fmaf(At[ty][f], Bt[tx][f], acc);
    Sout[((size_t)b*NN + i0 + ty)*NN + j0 + tx] = acc;
}

__global__ void rowsoftmax1024(float* __restrict__ S)
{
    int row = blockIdx.x;
    float* p = S + (size_t)row * 1024;
    int tid = threadIdx.x;   // 256
    float v[4];
    float m = -1e30f;
    #pragma unroll
    for (int q = 0; q < 4; ++q) { v[q] = p[tid + q*256]; m = fmaxf(m, v[q]); }
    __shared__ float red[8];
    __shared__ float red2[8];
    for (int o = 16; o >= 1; o >>= 1) m = fmaxf(m, __shfl_xor_sync(0xffffffffu, m, o));
    if ((tid & 31) == 0) red[tid >> 5] = m;
    __syncthreads();
    float mm = red[0];
    #pragma unroll
    for (int w = 1; w < 8; ++w) mm = fmaxf(mm, red[w]);
    float s = 0.f;
    #pragma unroll
    for (int q = 0; q < 4; ++q) { v[q] = expf(v[q] - mm); s += v[q]; }
    for (int o = 16; o >= 1; o >>= 1) s += __shfl_xor_sync(0xffffffffu, s, o);
    if ((tid & 31) == 0) red2[tid >> 5] = s;
    __syncthreads();
    float ss = 0.f;
    #pragma unroll
    for (int w = 0; w < 8; ++w) ss += red2[w];
    float inv = 1.f / ss;
    #pragma unroll
    for (int q = 0; q < 4; ++q) p[tid + q*256] = v[q] * inv;
}

// ---------------- attn_T = softmax(covT @ covT^T, axis=1) (column softmax!) --
__global__ void attnT_kernel(const float* __restrict__ tempE)
{
    __shared__ float cov[24][96];
    __shared__ float s[24][25];
    __shared__ float colmax[24], colsum[24];
    int b = blockIdx.x;
    int j = threadIdx.x, i = threadIdx.y;
    int tid = i*24 + j;
    for (int q = tid; q < 2304; q += 576) {
        int t = q / 96, f = q % 96;
        cov[t][f] = tempE[((b*TT + t)*NN)*FF + f];   // n = 0 slice
    }
    __syncthreads();
    float acc = 0.f;
    #pragma unroll
    for (int f = 0; f < 96; ++f) acc = fmaf(cov[i][f], cov[j][f], acc);
    s[i][j] = acc;
    __syncthreads();
    if (i == 0) {
        float m = -1e30f;
        for (int t = 0; t < 24; ++t) m = fmaxf(m, s[t][j]);
        colmax[j] = m;
    }
    __syncthreads();
    float e = expf(acc - colmax[j]);
    s[i][j] = e;
    __syncthreads();
    if (i == 0) {
        float sm = 0.f;
        for (int t = 0; t < 24; ++t) sm += s[t][j];
        colsum[j] = sm;
    }
    __syncthreads();
    g_attnT[(b*TT + i)*TT + j] = e / colsum[j];
}

// ---------------- temporal branch: per (b,n), all in smem ----------------
__global__ void temporal_kernel(const float* __restrict__ input)
{
    __shared__ float hgs[2304];
    __shared__ float xts[2304];
    __shared__ float xgs[2304];
    __shared__ float alph[2304];
    __shared__ float ats[576];
    __shared__ float elgs[96], ergs[96];
    int r = blockIdx.x;              // r = b*N + n
    int b = r >> 10, n = r & 1023;
    int tid = threadIdx.x;           // 256
    for (int q = tid; q < 2304; q += 256) hgs[q] = g_h[r*2304 + q];
    for (int q = tid; q < 2304; q += 256) {
        int t = q / 96, f = q % 96;
        xts[q] = input[((b*TT + t)*NN + n)*FF + f];
    }
    if (tid < 96) { elgs[tid] = g_el[r*96 + tid]; ergs[tid] = g_er[r*96 + tid]; }
    for (int q = tid; q < 576; q += 256) ats[q] = g_attnT[(n & 3)*576 + q]; // idx = r%B = n%4
    __syncthreads();
    if (tid < 96) {                  // softmax over j for (i,g)
        int i = tid >> 2, g = tid & 3;
        float eli = elgs[i*4 + g];
        float ev[24];
        float m = -1e30f;
        #pragma unroll
        for (int j = 0; j < 24; ++j) {
            float x = eli + ergs[j*4 + g];
            x = (x >= 0.f) ? x : 0.2f*x;
            ev[j] = x;
            m = fmaxf(m, x);
        }
        float s = 0.f;
        #pragma unroll
        for (int j = 0; j < 24; ++j) { ev[j] = expf(ev[j] - m); s += ev[j]; }
        float inv = 1.f / s;
        #pragma unroll
        for (int j = 0; j < 24; ++j) alph[tid*24 + j] = ev[j]*inv;
    }
    __syncthreads();
    for (int q = tid; q < 2304; q += 256) {   // xg = alpha @ hg
        int i = q / 96, rem = q % 96, g = rem / 24, d = rem % 24;
        float acc = 0.f;
        #pragma unroll
        for (int j = 0; j < 24; ++j)
            acc = fmaf(alph[(i*4+g)*24 + j], hgs[j*96 + g*24 + d], acc);
        xgs[q] = acc;
    }
    __syncthreads();
    for (int q = tid; q < 2304; q += 256) {   // emb gate + residual
        int i = q / 96, f = q % 96;
        float emb = 0.f;
        #pragma unroll
        for (int j = 0; j < 24; ++j) emb = fmaf(ats[i*24 + j], xts[j*96 + f], emb);
        float sg = 1.f / (1.f + expf(-emb));
        g_temporal[((b*TT + i)*NN + n)*FF + f] = xts[q] + xgs[q]*sg;
    }
}

// ---------------- fusion: z = sigmoid([sp,tp] @ Wf + bf); out = z*sp+(1-z)*tp+in
__global__ void fusion_kernel(const float* __restrict__ input, const float* __restrict__ Wf,
                              const float* __restrict__ bf, float* __restrict__ outp, int rgpb)
{
    extern __shared__ float4 Wfs[];            // 192*24 float4 = 73728 B
    __shared__ float4 sps4[4][24], tps4[4][24];
    __shared__ float bfs[96];
    int tid = threadIdx.x;                     // 96
    const float4* Wf4 = reinterpret_cast<const float4*>(Wf);
    for (int i = tid; i < 192*24; i += 96) Wfs[i] = Wf4[i];
    bfs[tid] = bf[tid];
    __syncthreads();
    int c = tid % 24, rg = tid / 24;
    const float* sps = reinterpret_cast<const float*>(sps4[rg]);
    const float* tps = reinterpret_cast<const float*>(tps4[rg]);
    for (int it = 0; it < rgpb; ++it) {
        int row = (blockIdx.x * rgpb + it) * 4 + rg;
        float4 s4 = reinterpret_cast<const float4*>(g_spatial + row*96)[c];
        float4 t4 = reinterpret_cast<const float4*>(g_temporal + row*96)[c];
        sps4[rg][c] = s4; tps4[rg][c] = t4;
        __syncthreads();
        int j0 = c*4;
        float4 acc = make_float4(bfs[j0], bfs[j0+1], bfs[j0+2], bfs[j0+3]);
        #pragma unroll
        for (int k = 0; k < 96; ++k) {
            float x = sps[k];
            float4 w = Wfs[k*24 + c];
            acc.x = fmaf(x, w.x, acc.x); acc.y = fmaf(x, w.y, acc.y);
            acc.z = fmaf(x, w.z, acc.z); acc.w = fmaf(x, w.w, acc.w);
        }
        #pragma unroll
        for (int k = 0; k < 96; ++k) {
            float x = tps[k];
            float4 w = Wfs[(96+k)*24 + c];
            acc.x = fmaf(x, w.x, acc.x); acc.y = fmaf(x, w.y, acc.y);
            acc.z = fmaf(x, w.z, acc.z); acc.w = fmaf(x, w.w, acc.w);
        }
        float4 z;
        z.x = 1.f/(1.f+expf(-acc.x)); z.y = 1.f/(1.f+expf(-acc.y));
        z.z = 1.f/(1.f+expf(-acc.z)); z.w = 1.f/(1.f+expf(-acc.w));
        float4 in4 = reinterpret_cast<const float4*>(input + row*96)[c];
        float4 o;
        o.x = z.x*s4.x + (1.f-z.x)*t4.x + in4.x;
        o.y = z.y*s4.y + (1.f-z.y)*t4.y + in4.y;
        o.z = z.z*s4.z + (1.f-z.z)*t4.z + in4.z;
        o.w = z.w*s4.w + (1.f-z.w)*t4.w + in4.w;
        reinterpret_cast<float4*>(outp + (size_t)row*96)[c] = o;
        __syncthreads();
    }
}

extern "C" void kernel_launch(void* const* d_in, const int* in_sizes, int n_in,
                              void* d_out, int out_size)
{
    const float* input = (const float*)d_in[0];
    const float* spatE = (const float*)d_in[1];
    const float* tempE = (const float*)d_in[2];
    const int*   srcs[3] = { (const int*)d_in[3], (const int*)d_in[5], (const int*)d_in[7] };
    const float* Ws_[3]  = { (const float*)d_in[9],  (const float*)d_in[13], (const float*)d_in[17] };
    const float* als_[3] = { (const float*)d_in[10], (const float*)d_in[14], (const float*)d_in[18] };
    const float* ars_[3] = { (const float*)d_in[11], (const float*)d_in[15], (const float*)d_in[19] };
    const float* bs_[3]  = { (const float*)d_in[12], (const float*)d_in[16], (const float*)d_in[20] };
    const float* Wg  = (const float*)d_in[21];
    const float* agl = (const float*)d_in[22];
    const float* agr = (const float*)d_in[23];
    const float* Wf  = (const float*)d_in[24];
    const float* bf  = (const float*)d_in[25];
    float* out   = (float*)d_out;
    float* attnS = out + (size_t)RR*96;   // out (B,T,N,F) then attn_S (B,N,N)

    // spatial GATs (sequential: g_h/g_el/g_er are reused)
    for (int g = 0; g < 3; ++g) {
        gemm96_fused<3><<<1024, 96>>>(input, spatE, Ws_[g], als_[g], ars_[g], 0, 24);
        gat_agg<<<RR/4, 128>>>(srcs[g], bs_[g], input, g);
    }
    // temporal projection (reuses g_h as hg, g_el/g_er as elg/erg)
    gemm96_fused<4><<<1024, 96>>>(input, input, Wg, agl, agr, 1, 24);

    // attn_S (second output): scores then in-place row softmax
    attnS_gemm<<<dim3(32,32,4), dim3(32,32)>>>(spatE, attnS);
    rowsoftmax1024<<<4096, 256>>>(attnS);

    // attn_T (tiny, column softmax)
    attnT_kernel<<<4, dim3(24,24)>>>(tempE);

    // temporal branch
    temporal_kernel<<<4096, 256>>>(input);

    // fusion
    cudaFuncSetAttribute(fusion_kernel, cudaFuncAttributeMaxDynamicSharedMemorySize, 73728);
    fusion_kernel<<<1024, 96, 73728>>>(input, Wf, bf, out, 24);
}

// round 6
// speedup vs baseline: 1.9650x; 1.9636x over previous
#include <cuda_runtime.h>
#include <math.h>

#define NN 1024
#define BB 4
#define TT 24
#define FF 96
#define RR (NN*96)       // 98304 rows (== B*T*N)
#define RGRID (RR/128)   // 768

// ---------------- scratch (device globals; no allocs allowed) ----------------
__device__ float g_h3[3*(size_t)RR*96];   // spatial GAT h, per gat
__device__ float g_el3[3*RR*3];
__device__ float g_er3[3*RR*3];
__device__ float g_hg[(size_t)RR*96];     // temporal hg, row = (b*N+n)*24+t
__device__ float g_elg[RR*4];
__device__ float g_erg[RR*4];
__device__ float g_spatial[(size_t)RR*96];
__device__ float g_temporal[(size_t)RR*96];
__device__ float g_attnT[BB*TT*TT];

// =============== big fused GEMM: 128 rows x 96 cols per block =================
// MODE 0 (spatial): row = n*96 + k (k = t*B+b), x = input + spatial_emb,
//                   gat = blockIdx.y, writes g_h3/g_el3/g_er3 (HEADS=3)
// MODE 1 (temporal): row = (b*N+n)*24 + t, x = input, writes g_hg/g_elg/g_erg (HEADS=4)
template<int HEADS, int MODE>
__global__ __launch_bounds__(384)
void gemm_big(const float* __restrict__ X, const float* __restrict__ Emb,
              const float* __restrict__ W0, const float* __restrict__ W1, const float* __restrict__ W2,
              const float* __restrict__ al0, const float* __restrict__ al1, const float* __restrict__ al2,
              const float* __restrict__ ar0, const float* __restrict__ ar1, const float* __restrict__ ar2)
{
    extern __shared__ float sm[];
    float* Xs  = sm;                 // [96][132] k-major
    float* Ws  = sm + 96*132;        // [96][96]  k-major
    float* pel = Ws + 96*96;         // [128][12]
    float* per = pel + 128*12;       // [128][12]

    const int tid = threadIdx.x;     // 384
    const int gat = (MODE == 0) ? blockIdx.y : 0;
    const float* W  = (gat == 0) ? W0  : (gat == 1) ? W1  : W2;
    const float* al = (gat == 0) ? al0 : (gat == 1) ? al1 : al2;
    const float* ar = (gat == 0) ? ar0 : (gat == 1) ? ar1 : ar2;
    const int row0 = blockIdx.x * 128;

    // load W (k-major already: W[k*96+c])
    {
        const float4* W4 = reinterpret_cast<const float4*>(W);
        float4* Ws4 = reinterpret_cast<float4*>(Ws);
        for (int i = tid; i < 96*24; i += 384) Ws4[i] = W4[i];
    }
    // load X tile, store transposed (k-major)
    #pragma unroll
    for (int i = 0; i < 8; ++i) {
        int idx = tid + i*384;            // < 3072
        int r = idx / 24, c4 = idx % 24;
        int gr = row0 + r;
        int off;
        if (MODE == 0) {
            int n = gr / 96, k = gr % 96;
            int b = k & 3, t = k >> 2;
            off = ((b*TT + t)*NN + n)*FF;
        } else {
            int rr = gr / 24, t = gr % 24;
            int b = rr >> 10, n = rr & 1023;
            off = ((b*TT + t)*NN + n)*FF;
        }
        float4 v = *reinterpret_cast<const float4*>(X + off + c4*4);
        if (MODE == 0) {
            float4 e = *reinterpret_cast<const float4*>(Emb + off + c4*4);
            v.x += e.x; v.y += e.y; v.z += e.z; v.w += e.w;
        }
        Xs[(c4*4+0)*132 + r] = v.x;
        Xs[(c4*4+1)*132 + r] = v.y;
        Xs[(c4*4+2)*132 + r] = v.z;
        Xs[(c4*4+3)*132 + r] = v.w;
    }
    __syncthreads();

    const int lane = tid & 31, cg = tid >> 5;   // cg 0..11 (8 cols each)
    float acc[4][8];
    #pragma unroll
    for (int u = 0; u < 4; ++u)
        #pragma unroll
        for (int c = 0; c < 8; ++c) acc[u][c] = 0.f;

    #pragma unroll 8
    for (int k = 0; k < 96; ++k) {
        float4 xv = *reinterpret_cast<float4*>(&Xs[k*132 + lane*4]);
        float4 wa = *reinterpret_cast<float4*>(&Ws[k*96 + cg*8]);
        float4 wb = *reinterpret_cast<float4*>(&Ws[k*96 + cg*8 + 4]);
        float xr[4] = {xv.x, xv.y, xv.z, xv.w};
        float wc[8] = {wa.x, wa.y, wa.z, wa.w, wb.x, wb.y, wb.z, wb.w};
        #pragma unroll
        for (int u = 0; u < 4; ++u)
            #pragma unroll
            for (int c = 0; c < 8; ++c)
                acc[u][c] = fmaf(xr[u], wc[c], acc[u][c]);
    }

    // write H
    float* Hb = (MODE == 0) ? (g_h3 + (size_t)gat*RR*96) : g_hg;
    #pragma unroll
    for (int u = 0; u < 4; ++u) {
        int gr = row0 + lane*4 + u;
        float4 o0 = make_float4(acc[u][0], acc[u][1], acc[u][2], acc[u][3]);
        float4 o1 = make_float4(acc[u][4], acc[u][5], acc[u][6], acc[u][7]);
        float4* p = reinterpret_cast<float4*>(Hb + (size_t)gr*96 + cg*8);
        p[0] = o0; p[1] = o1;
    }
    // per-thread partial el/er (8 cols live in a single head: 8 | 32 and 8 | 24)
    float alv[8], arv[8];
    #pragma unroll
    for (int c = 0; c < 8; ++c) { alv[c] = al[cg*8 + c]; arv[c] = ar[cg*8 + c]; }
    #pragma unroll
    for (int u = 0; u < 4; ++u) {
        float sl = 0.f, sr = 0.f;
        #pragma unroll
        for (int c = 0; c < 8; ++c) { sl = fmaf(acc[u][c], alv[c], sl); sr = fmaf(acc[u][c], arv[c], sr); }
        pel[(lane*4+u)*12 + cg] = sl;
        per[(lane*4+u)*12 + cg] = sr;
    }
    __syncthreads();
    const int QW = 12 / HEADS;          // 4 (H=3) or 3 (GH=4)
    // NOTE: 128*HEADS can exceed blockDim (512 for HEADS=4) -> strided loop.
    for (int q0 = tid; q0 < 128*HEADS; q0 += 384) {
        int r = q0 / HEADS, h = q0 % HEADS;
        float sl = 0.f, sr = 0.f;
        #pragma unroll
        for (int q = 0; q < 4; ++q) {
            if (q < QW) { sl += pel[r*12 + h*QW + q]; sr += per[r*12 + h*QW + q]; }
        }
        int gr = row0 + r;
        if (MODE == 0) {
            g_el3[(size_t)gat*RR*3 + gr*3 + h] = sl;
            g_er3[(size_t)gat*RR*3 + gr*3 + h] = sr;
        } else {
            g_elg[gr*4 + h] = sl;
            g_erg[gr*4 + h] = sr;
        }
    }
}

// ---------------- GAT edge softmax + aggregation (all 3 gats, grid.y) --------
__global__ void gat_agg(const int* __restrict__ src0, const int* __restrict__ src1,
                        const int* __restrict__ src2,
                        const float* __restrict__ bias0, const float* __restrict__ bias1,
                        const float* __restrict__ bias2,
                        const float* __restrict__ inp)
{
    int gat = blockIdx.y;
    const int*   src  = (gat == 0) ? src0  : (gat == 1) ? src1  : src2;
    const float* bias = (gat == 0) ? bias0 : (gat == 1) ? bias1 : bias2;
    const float* H  = g_h3  + (size_t)gat*RR*96;
    const float* EL = g_el3 + (size_t)gat*RR*3;
    const float* ER = g_er3 + (size_t)gat*RR*3;

    int gw = blockIdx.x * 4 + (threadIdx.x >> 5);
    int lane = threadIdx.x & 31;
    int n = gw / 96, k = gw % 96;
    int srcj = 0;
    if (lane < 8) srcj = src[n + lane*NN];
    float val = 0.f;
    #pragma unroll
    for (int hh = 0; hh < 3; ++hh) {
        float myer = ER[(n*96 + k)*3 + hh];
        float e = -1e30f;
        if (lane < 8) {
            float x = EL[(srcj*96 + k)*3 + hh] + myer;
            e = (x >= 0.f) ? x : 0.2f*x;
        }
        float m = e;
        m = fmaxf(m, __shfl_down_sync(0xffffffffu, m, 4));
        m = fmaxf(m, __shfl_down_sync(0xffffffffu, m, 2));
        m = fmaxf(m, __shfl_down_sync(0xffffffffu, m, 1));
        m = __shfl_sync(0xffffffffu, m, 0);
        float ex = (lane < 8) ? expf(e - m) : 0.f;
        float s = ex;
        s += __shfl_down_sync(0xffffffffu, s, 4);
        s += __shfl_down_sync(0xffffffffu, s, 2);
        s += __shfl_down_sync(0xffffffffu, s, 1);
        s = __shfl_sync(0xffffffffu, s, 0);
        float inv = 1.f / (s + 1e-9f);
        float acc = 0.f;
        #pragma unroll
        for (int j = 0; j < 8; ++j) {
            float aj = __shfl_sync(0xffffffffu, ex, j) * inv;
            int   sj = __shfl_sync(0xffffffffu, srcj, j);
            acc = fmaf(aj, H[((size_t)sj*96 + k)*96 + hh*32 + lane], acc);
        }
        val += acc + bias[hh*32 + lane];
    }
    val *= (1.f/3.f);
    int ob = k / 24, ot = k % 24;        // reference's reshape scramble
    size_t o = (size_t)((ob*TT + ot)*NN + n)*FF + gat*32 + lane;
    g_spatial[o] = inp[o] + val;
}

// ---------------- attn_S = softmax(cov0 @ cov0^T, axis=2) --------------------
__global__ __launch_bounds__(256)
void attnS_gemm(const float* __restrict__ spatE, float* __restrict__ Sout)
{
    extern __shared__ float sm2[];
    float* At = sm2;            // [64][97]
    float* Bt = sm2 + 64*97;    // [64][97]
    int b = blockIdx.z;
    int i0 = blockIdx.y * 64, j0 = blockIdx.x * 64;
    const float* cov = spatE + (size_t)b*TT*NN*FF;   // t = 0 slice
    int tid = threadIdx.x;       // 256
    #pragma unroll
    for (int i = 0; i < 6; ++i) {
        int idx = tid + i*256;   // < 1536
        int r = idx / 24, c4 = idx % 24;
        float4 v = *reinterpret_cast<const float4*>(cov + (i0 + r)*96 + c4*4);
        At[r*97 + c4*4+0] = v.x; At[r*97 + c4*4+1] = v.y;
        At[r*97 + c4*4+2] = v.z; At[r*97 + c4*4+3] = v.w;
        float4 w = *reinterpret_cast<const float4*>(cov + (j0 + r)*96 + c4*4);
        Bt[r*97 + c4*4+0] = w.x; Bt[r*97 + c4*4+1] = w.y;
        Bt[r*97 + c4*4+2] = w.z; Bt[r*97 + c4*4+3] = w.w;
    }
    __syncthreads();
    int tx = tid & 15, ty = tid >> 4;
    float acc[4][4];
    #pragma unroll
    for (int u = 0; u < 4; ++u)
        #pragma unroll
        for (int v = 0; v < 4; ++v) acc[u][v] = 0.f;
    #pragma unroll 8
    for (int f = 0; f < 96; ++f) {
        float a[4], bb[4];
        #pragma unroll
        for (int u = 0; u < 4; ++u) a[u] = At[(ty*4+u)*97 + f];
        #pragma unroll
        for (int v = 0; v < 4; ++v) bb[v] = Bt[(tx*4+v)*97 + f];
        #pragma unroll
        for (int u = 0; u < 4; ++u)
            #pragma unroll
            for (int v = 0; v < 4; ++v) acc[u][v] = fmaf(a[u], bb[v], acc[u][v]);
    }
    #pragma unroll
    for (int u = 0; u < 4; ++u) {
        float4 o = make_float4(acc[u][0], acc[u][1], acc[u][2], acc[u][3]);
        *reinterpret_cast<float4*>(Sout + ((size_t)b*NN + i0 + ty*4 + u)*NN + j0 + tx*4) = o;
    }
}

__global__ void rowsoftmax1024(float* __restrict__ S)
{
    int row = blockIdx.x;
    float* p = S + (size_t)row * 1024;
    int tid = threadIdx.x;   // 256
    float v[4];
    float m = -1e30f;
    #pragma unroll
    for (int q = 0; q < 4; ++q) { v[q] = p[tid + q*256]; m = fmaxf(m, v[q]); }
    __shared__ float red[8];
    __shared__ float red2[8];
    for (int o = 16; o >= 1; o >>= 1) m = fmaxf(m, __shfl_xor_sync(0xffffffffu, m, o));
    if ((tid & 31) == 0) red[tid >> 5] = m;
    __syncthreads();
    float mm = red[0];
    #pragma unroll
    for (int w = 1; w < 8; ++w) mm = fmaxf(mm, red[w]);
    float s = 0.f;
    #pragma unroll
    for (int q = 0; q < 4; ++q) { v[q] = expf(v[q] - mm); s += v[q]; }
    for (int o = 16; o >= 1; o >>= 1) s += __shfl_xor_sync(0xffffffffu, s, o);
    if ((tid & 31) == 0) red2[tid >> 5] = s;
    __syncthreads();
    float ss = 0.f;
    #pragma unroll
    for (int w = 0; w < 8; ++w) ss += red2[w];
    float inv = 1.f / ss;
    #pragma unroll
    for (int q = 0; q < 4; ++q) p[tid + q*256] = v[q] * inv;
}

// ---------------- attn_T = softmax(covT @ covT^T, axis=1) --------------------
__global__ void attnT_kernel(const float* __restrict__ tempE)
{
    __shared__ float cov[24][96];
    __shared__ float s[24][25];
    __shared__ float colmax[24], colsum[24];
    int b = blockIdx.x;
    int j = threadIdx.x, i = threadIdx.y;
    int tid = i*24 + j;
    for (int q = tid; q < 2304; q += 576) {
        int t = q / 96, f = q % 96;
        cov[t][f] = tempE[((b*TT + t)*NN)*FF + f];   // n = 0 slice
    }
    __syncthreads();
    float acc = 0.f;
    #pragma unroll
    for (int f = 0; f < 96; ++f) acc = fmaf(cov[i][f], cov[j][f], acc);
    s[i][j] = acc;
    __syncthreads();
    if (i == 0) {
        float m = -1e30f;
        for (int t = 0; t < 24; ++t) m = fmaxf(m, s[t][j]);
        colmax[j] = m;
    }
    __syncthreads();
    float e = expf(acc - colmax[j]);
    s[i][j] = e;
    __syncthreads();
    if (i == 0) {
        float sm0 = 0.f;
        for (int t = 0; t < 24; ++t) sm0 += s[t][j];
        colsum[j] = sm0;
    }
    __syncthreads();
    g_attnT[(b*TT + i)*TT + j] = e / colsum[j];
}

// ---------------- temporal branch: per (b,n), all in smem --------------------
__global__ void temporal_kernel(const float* __restrict__ input)
{
    __shared__ float hgs[2304];
    __shared__ float xts[2304];
    __shared__ float xgs[2304];
    __shared__ float alph[2304];
    __shared__ float ats[576];
    __shared__ float elgs[96], ergs[96];
    int r = blockIdx.x;              // r = b*N + n
    int b = r >> 10, n = r & 1023;
    int tid = threadIdx.x;           // 256
    for (int q = tid; q < 2304; q += 256) hgs[q] = g_hg[(size_t)r*2304 + q];
    for (int q = tid; q < 2304; q += 256) {
        int t = q / 96, f = q % 96;
        xts[q] = input[((b*TT + t)*NN + n)*FF + f];
    }
    if (tid < 96) { elgs[tid] = g_elg[r*96 + tid]; ergs[tid] = g_erg[r*96 + tid]; }
    for (int q = tid; q < 576; q += 256) ats[q] = g_attnT[(n & 3)*576 + q]; // idx = r%B = n%4
    __syncthreads();
    if (tid < 96) {                  // softmax over j for (i,g)
        int i = tid >> 2, g = tid & 3;
        float eli = elgs[i*4 + g];
        float ev[24];
        float m = -1e30f;
        #pragma unroll
        for (int j = 0; j < 24; ++j) {
            float x = eli + ergs[j*4 + g];
            x = (x >= 0.f) ? x : 0.2f*x;
            ev[j] = x;
            m = fmaxf(m, x);
        }
        float s = 0.f;
        #pragma unroll
        for (int j = 0; j < 24; ++j) { ev[j] = expf(ev[j] - m); s += ev[j]; }
        float inv = 1.f / s;
        #pragma unroll
        for (int j = 0; j < 24; ++j) alph[tid*24 + j] = ev[j]*inv;
    }
    __syncthreads();
    for (int q = tid; q < 2304; q += 256) {   // xg = alpha @ hg
        int i = q / 96, rem = q % 96, g = rem / 24, d = rem % 24;
        float acc = 0.f;
        #pragma unroll
        for (int j = 0; j < 24; ++j)
            acc = fmaf(alph[(i*4+g)*24 + j], hgs[j*96 + g*24 + d], acc);
        xgs[q] = acc;
    }
    __syncthreads();
    for (int q = tid; q < 2304; q += 256) {   // emb gate + residual
        int i = q / 96, f = q % 96;
        float emb = 0.f;
        #pragma unroll
        for (int j = 0; j < 24; ++j) emb = fmaf(ats[i*24 + j], xts[j*96 + f], emb);
        float sg = 1.f / (1.f + expf(-emb));
        g_temporal[(size_t)((b*TT + i)*NN + n)*FF + f] = xts[q] + xgs[q]*sg;
    }
}

// ---------------- fusion: z = sigmoid([sp,tp]@Wf + bf); out = z*sp+(1-z)*tp+in
__global__ __launch_bounds__(384)
void fusion_kernel(const float* __restrict__ input, const float* __restrict__ Wf,
                   const float* __restrict__ bf, float* __restrict__ outp)
{
    extern __shared__ float sm[];
    float* Xs = sm;               // [192][132] k-major
    float* Ws = sm + 192*132;     // [192][96]
    int tid = threadIdx.x;        // 384
    const float4* W4 = reinterpret_cast<const float4*>(Wf);
    float4* Ws4 = reinterpret_cast<float4*>(Ws);
    for (int i = tid; i < 192*24; i += 384) Ws4[i] = W4[i];
    int row0 = blockIdx.x * 128;
    #pragma unroll
    for (int i = 0; i < 16; ++i) {
        int idx = tid + i*384;            // < 6144
        int r = idx / 48, c4 = idx % 48;
        int gr = row0 + r;
        const float* src = (c4 < 24) ? g_spatial : g_temporal;
        int cc = (c4 < 24) ? c4 : c4 - 24;
        float4 v = *reinterpret_cast<const float4*>(src + (size_t)gr*96 + cc*4);
        int kb = (c4 < 24 ? 0 : 96) + cc*4;
        Xs[(kb+0)*132 + r] = v.x;
        Xs[(kb+1)*132 + r] = v.y;
        Xs[(kb+2)*132 + r] = v.z;
        Xs[(kb+3)*132 + r] = v.w;
    }
    __syncthreads();
    int lane = tid & 31, cg = tid >> 5;
    float acc[4][8];
    #pragma unroll
    for (int u = 0; u < 4; ++u)
        #pragma unroll
        for (int c = 0; c < 8; ++c) acc[u][c] = 0.f;
    #pragma unroll 8
    for (int k = 0; k < 192; ++k) {
        float4 xv = *reinterpret_cast<float4*>(&Xs[k*132 + lane*4]);
        float4 wa = *reinterpret_cast<float4*>(&Ws[k*96 + cg*8]);
        float4 wb = *reinterpret_cast<float4*>(&Ws[k*96 + cg*8 + 4]);
        float xr[4] = {xv.x, xv.y, xv.z, xv.w};
        float wc[8] = {wa.x, wa.y, wa.z, wa.w, wb.x, wb.y, wb.z, wb.w};
        #pragma unroll
        for (int u = 0; u < 4; ++u)
            #pragma unroll
            for (int c = 0; c < 8; ++c)
                acc[u][c] = fmaf(xr[u], wc[c], acc[u][c]);
    }
    float bfv[8];
    #pragma unroll
    for (int c = 0; c < 8; ++c) bfv[c] = bf[cg*8 + c];
    #pragma unroll
    for (int u = 0; u < 4; ++u) {
        int gr = row0 + lane*4 + u;
        int rl = lane*4 + u;
        float4 i0 = *reinterpret_cast<const float4*>(input + (size_t)gr*96 + cg*8);
        float4 i1 = *reinterpret_cast<const float4*>(input + (size_t)gr*96 + cg*8 + 4);
        float inv[8] = {i0.x, i0.y, i0.z, i0.w, i1.x, i1.y, i1.z, i1.w};
        float o[8];
        #pragma unroll
        for (int c = 0; c < 8; ++c) {
            float z = 1.f / (1.f + expf(-(acc[u][c] + bfv[c])));
            float sp = Xs[(cg*8 + c)*132 + rl];
            float tp = Xs[(96 + cg*8 + c)*132 + rl];
            o[c] = z*sp + (1.f - z)*tp + inv[c];
        }
        float4* p = reinterpret_cast<float4*>(outp + (size_t)gr*96 + cg*8);
        p[0] = make_float4(o[0], o[1], o[2], o[3]);
        p[1] = make_float4(o[4], o[5], o[6], o[7]);
    }
}

extern "C" void kernel_launch(void* const* d_in, const int* in_sizes, int n_in,
                              void* d_out, int out_size)
{
    const float* input = (const float*)d_in[0];
    const float* spatE = (const float*)d_in[1];
    const float* tempE = (const float*)d_in[2];
    const int*   s0 = (const int*)d_in[3];
    const int*   s1 = (const int*)d_in[5];
    const int*   s2 = (const int*)d_in[7];
    const float* W_d = (const float*)d_in[9];
    const float* al_d = (const float*)d_in[10];
    const float* ar_d = (const float*)d_in[11];
    const float* b_d = (const float*)d_in[12];
    const float* W_m = (const float*)d_in[13];
    const float* al_m = (const float*)d_in[14];
    const float* ar_m = (const float*)d_in[15];
    const float* b_m = (const float*)d_in[16];
    const float* W_s = (const float*)d_in[17];
    const float* al_s = (const float*)d_in[18];
    const float* ar_s = (const float*)d_in[19];
    const float* b_s = (const float*)d_in[20];
    const float* Wg  = (const float*)d_in[21];
    const float* agl = (const float*)d_in[22];
    const float* agr = (const float*)d_in[23];
    const float* Wf  = (const float*)d_in[24];
    const float* bf  = (const float*)d_in[25];
    float* out   = (float*)d_out;
    float* attnS = out + (size_t)RR*96;   // out (B,T,N,F) then attn_S (B,N,N)

    const int GEMM_SMEM = (96*132 + 96*96 + 2*128*12) * 4;     //  99,840 B
    const int FUS_SMEM  = (192*132 + 192*96) * 4;              // 175,104 B
    const int ATS_SMEM  = (2*64*97) * 4;                       //  49,664 B
    static int attrs_set = 0;
    if (!attrs_set) {
        cudaFuncSetAttribute(gemm_big<3,0>, cudaFuncAttributeMaxDynamicSharedMemorySize, GEMM_SMEM);
        cudaFuncSetAttribute(gemm_big<4,1>, cudaFuncAttributeMaxDynamicSharedMemorySize, GEMM_SMEM);
        cudaFuncSetAttribute(fusion_kernel, cudaFuncAttributeMaxDynamicSharedMemorySize, FUS_SMEM);
        cudaFuncSetAttribute(attnS_gemm,    cudaFuncAttributeMaxDynamicSharedMemorySize, ATS_SMEM);
        attrs_set = 1;
    }

    // spatial GATs: one fused GEMM launch (grid.y = gat), then fused aggregation
    gemm_big<3,0><<<dim3(RGRID,3), 384, GEMM_SMEM>>>(input, spatE,
        W_d, W_m, W_s, al_d, al_m, al_s, ar_d, ar_m, ar_s);
    // temporal projection (independent of gat_agg)
    gemm_big<4,1><<<dim3(RGRID,1), 384, GEMM_SMEM>>>(input, input,
        Wg, Wg, Wg, agl, agl, agl, agr, agr, agr);

    gat_agg<<<dim3(RR/4,3), 128>>>(s0, s1, s2, b_d, b_m, b_s, input);

    // attn_S (second output)
    attnS_gemm<<<dim3(16,16,4), 256, ATS_SMEM>>>(spatE, attnS);
    rowsoftmax1024<<<4096, 256>>>(attnS);

    // attn_T (tiny) + temporal branch
    attnT_kernel<<<4, dim3(24,24)>>>(tempE);
    temporal_kernel<<<4096, 256>>>(input);

    // fusion
    fusion_kernel<<<RGRID, 384, FUS_SMEM>>>(input, Wf, bf, out);
}

// round 7
// speedup vs baseline: 2.3392x; 1.1904x over previous
#include <cuda_runtime.h>
#include <math.h>
#include <stdint.h>

#define NN 1024
#define BB 4
#define TT 24
#define FF 96
#define RR (NN*96)       // 98304 rows (== B*T*N)
#define RGRID (RR/128)   // 768

// ---------------- scratch (device globals; no allocs allowed) ----------------
__device__ float g_h3[3*(size_t)RR*96];   // spatial GAT h, per gat
__device__ float g_el3[3*RR*3];
__device__ float g_er3[3*RR*3];
__device__ float g_hg[(size_t)RR*96];     // temporal hg, row = (b*N+n)*24+t
__device__ float g_elg[RR*4];
__device__ float g_erg[RR*4];
__device__ float g_spatial[(size_t)RR*96];
__device__ float g_temporal[(size_t)RR*96];
__device__ float g_attnT[BB*TT*TT];

// ---------------- tf32 helpers ----------------
__device__ __forceinline__ uint32_t f2tf32(float x) {
    uint32_t r; asm("cvt.rna.tf32.f32 %0, %1;" : "=r"(r) : "f"(x)); return r;
}
__device__ __forceinline__ void mma_tf32(float* c, const uint32_t* a, uint32_t b0, uint32_t b1) {
    asm volatile("mma.sync.aligned.m16n8k8.row.col.f32.tf32.tf32.f32 "
        "{%0,%1,%2,%3}, {%4,%5,%6,%7}, {%8,%9}, {%0,%1,%2,%3};"
        : "+f"(c[0]), "+f"(c[1]), "+f"(c[2]), "+f"(c[3])
        : "r"(a[0]), "r"(a[1]), "r"(a[2]), "r"(a[3]), "r"(b0), "r"(b1));
}

// =============== tensor-core fused GEMM: 128 rows x 96 cols per block ========
// MODE 0 (spatial): row = n*96 + k (k = t*B+b), x = input + spatial_emb,
//                   gat = blockIdx.y, writes g_h3/g_el3/g_er3 (HEADS=3)
// MODE 1 (temporal): row = (b*N+n)*24 + t, x = input, writes g_hg/g_elg/g_erg (HEADS=4)
// 256 threads = 8 warps; warp w -> rows [w*16, w*16+16); 12 n-tiles of 8 cols.
template<int HEADS, int MODE>
__global__ __launch_bounds__(256)
void gemm_tc(const float* __restrict__ X, const float* __restrict__ Emb,
             const float* __restrict__ W0, const float* __restrict__ W1, const float* __restrict__ W2,
             const float* __restrict__ al0, const float* __restrict__ al1, const float* __restrict__ al2,
             const float* __restrict__ ar0, const float* __restrict__ ar1, const float* __restrict__ ar2)
{
    extern __shared__ float sm[];
    float*    Xs = sm;                                 // [128][100] fp32
    uint32_t* Ws = (uint32_t*)(sm + 128*100);          // [96][104]  tf32

    const int tid = threadIdx.x;
    const int gat = (MODE == 0) ? blockIdx.y : 0;
    const float* W  = (gat == 0) ? W0  : (gat == 1) ? W1  : W2;
    const float* al = (gat == 0) ? al0 : (gat == 1) ? al1 : al2;
    const float* ar = (gat == 0) ? ar0 : (gat == 1) ? ar1 : ar2;
    const int row0 = blockIdx.x * 128;

    // W -> smem, tf32-converted, pitch 104 (bank-conflict-free B-frag loads)
    for (int i = tid; i < 96*24; i += 256) {
        int k = i / 24, c4 = i % 24;
        float4 v = reinterpret_cast<const float4*>(W)[i];
        *reinterpret_cast<uint4*>(&Ws[k*104 + c4*4]) =
            make_uint4(f2tf32(v.x), f2tf32(v.y), f2tf32(v.z), f2tf32(v.w));
    }
    // X tile -> smem fp32, row-major pitch 100
    for (int i = tid; i < 3072; i += 256) {
        int r = i / 24, c4 = i % 24;
        int gr = row0 + r;
        int off;
        if (MODE == 0) {
            int n = gr / 96, k = gr % 96;
            int b = k & 3, t = k >> 2;
            off = ((b*TT + t)*NN + n)*FF;
        } else {
            int rr = gr / 24, t = gr % 24;
            int b = rr >> 10, n = rr & 1023;
            off = ((b*TT + t)*NN + n)*FF;
        }
        float4 v = *reinterpret_cast<const float4*>(X + off + c4*4);
        if (MODE == 0) {
            float4 e = *reinterpret_cast<const float4*>(Emb + off + c4*4);
            v.x += e.x; v.y += e.y; v.z += e.z; v.w += e.w;
        }
        *reinterpret_cast<float4*>(&Xs[r*100 + c4*4]) = v;
    }
    __syncthreads();

    const int lane = tid & 31, w = tid >> 5;
    const int g = lane >> 2, tig = lane & 3;
    const int r0 = w * 16;

    float acc[12][4];
    #pragma unroll
    for (int nt = 0; nt < 12; ++nt)
        #pragma unroll
        for (int q = 0; q < 4; ++q) acc[nt][q] = 0.f;

    #pragma unroll
    for (int ks = 0; ks < 12; ++ks) {
        int k0 = ks * 8;
        uint32_t a[4];
        a[0] = f2tf32(Xs[(r0+g  )*100 + k0 + tig    ]);
        a[1] = f2tf32(Xs[(r0+g+8)*100 + k0 + tig    ]);
        a[2] = f2tf32(Xs[(r0+g  )*100 + k0 + tig + 4]);
        a[3] = f2tf32(Xs[(r0+g+8)*100 + k0 + tig + 4]);
        #pragma unroll
        for (int nt = 0; nt < 12; ++nt) {
            uint32_t b0 = Ws[(k0+tig  )*104 + nt*8 + g];
            uint32_t b1 = Ws[(k0+tig+4)*104 + nt*8 + g];
            mma_tf32(acc[nt], a, b0, b1);
        }
    }

    // write H: thread owns rows gr0, gr1 (cols nt*8 + 2tig, +1)
    float* Hb = (MODE == 0) ? (g_h3 + (size_t)gat*RR*96) : g_hg;
    const int gr0 = row0 + r0 + g, gr1 = gr0 + 8;
    #pragma unroll
    for (int nt = 0; nt < 12; ++nt) {
        *reinterpret_cast<float2*>(Hb + (size_t)gr0*96 + nt*8 + 2*tig) = make_float2(acc[nt][0], acc[nt][1]);
        *reinterpret_cast<float2*>(Hb + (size_t)gr1*96 + nt*8 + 2*tig) = make_float2(acc[nt][2], acc[nt][3]);
    }

    // el/er epilogue: per-head dot with al/ar, reduce over tig quad via shfl
    const int NTH = 12 / HEADS;       // 4 (HEADS=3) or 3 (HEADS=4)
    #pragma unroll
    for (int h = 0; h < HEADS; ++h) {
        float sl0 = 0.f, sr0 = 0.f, sl1 = 0.f, sr1 = 0.f;
        #pragma unroll
        for (int q = 0; q < NTH; ++q) {
            int nt = h*NTH + q;
            float a0 = al[nt*8 + 2*tig], a1 = al[nt*8 + 2*tig + 1];
            float c0 = ar[nt*8 + 2*tig], c1 = ar[nt*8 + 2*tig + 1];
            sl0 += acc[nt][0]*a0 + acc[nt][1]*a1;
            sr0 += acc[nt][0]*c0 + acc[nt][1]*c1;
            sl1 += acc[nt][2]*a0 + acc[nt][3]*a1;
            sr1 += acc[nt][2]*c0 + acc[nt][3]*c1;
        }
        sl0 += __shfl_xor_sync(0xffffffffu, sl0, 1); sl0 += __shfl_xor_sync(0xffffffffu, sl0, 2);
        sr0 += __shfl_xor_sync(0xffffffffu, sr0, 1); sr0 += __shfl_xor_sync(0xffffffffu, sr0, 2);
        sl1 += __shfl_xor_sync(0xffffffffu, sl1, 1); sl1 += __shfl_xor_sync(0xffffffffu, sl1, 2);
        sr1 += __shfl_xor_sync(0xffffffffu, sr1, 1); sr1 += __shfl_xor_sync(0xffffffffu, sr1, 2);
        if (tig == 0) {
            if (MODE == 0) {
                g_el3[(size_t)gat*RR*3 + gr0*3 + h] = sl0;
                g_er3[(size_t)gat*RR*3 + gr0*3 + h] = sr0;
                g_el3[(size_t)gat*RR*3 + gr1*3 + h] = sl1;
                g_er3[(size_t)gat*RR*3 + gr1*3 + h] = sr1;
            } else {
                g_elg[gr0*4 + h] = sl0;  g_erg[gr0*4 + h] = sr0;
                g_elg[gr1*4 + h] = sl1;  g_erg[gr1*4 + h] = sr1;
            }
        }
    }
}

// ---------------- GAT edge softmax + aggregation (all 3 gats, grid.y) --------
__global__ void gat_agg(const int* __restrict__ src0, const int* __restrict__ src1,
                        const int* __restrict__ src2,
                        const float* __restrict__ bias0, const float* __restrict__ bias1,
                        const float* __restrict__ bias2,
                        const float* __restrict__ inp)
{
    int gat = blockIdx.y;
    const int*   src  = (gat == 0) ? src0  : (gat == 1) ? src1  : src2;
    const float* bias = (gat == 0) ? bias0 : (gat == 1) ? bias1 : bias2;
    const float* H  = g_h3  + (size_t)gat*RR*96;
    const float* EL = g_el3 + (size_t)gat*RR*3;
    const float* ER = g_er3 + (size_t)gat*RR*3;

    int gw = blockIdx.x * 4 + (threadIdx.x >> 5);
    int lane = threadIdx.x & 31;
    int n = gw / 96, k = gw % 96;
    int srcj = 0;
    if (lane < 8) srcj = src[n + lane*NN];
    float val = 0.f;
    #pragma unroll
    for (int hh = 0; hh < 3; ++hh) {
        float myer = ER[(n*96 + k)*3 + hh];
        float e = -1e30f;
        if (lane < 8) {
            float x = EL[(srcj*96 + k)*3 + hh] + myer;
            e = (x >= 0.f) ? x : 0.2f*x;
        }
        float m = e;
        m = fmaxf(m, __shfl_down_sync(0xffffffffu, m, 4));
        m = fmaxf(m, __shfl_down_sync(0xffffffffu, m, 2));
        m = fmaxf(m, __shfl_down_sync(0xffffffffu, m, 1));
        m = __shfl_sync(0xffffffffu, m, 0);
        float ex = (lane < 8) ? expf(e - m) : 0.f;
        float s = ex;
        s += __shfl_down_sync(0xffffffffu, s, 4);
        s += __shfl_down_sync(0xffffffffu, s, 2);
        s += __shfl_down_sync(0xffffffffu, s, 1);
        s = __shfl_sync(0xffffffffu, s, 0);
        float inv = 1.f / (s + 1e-9f);
        float acc = 0.f;
        #pragma unroll
        for (int j = 0; j < 8; ++j) {
            float aj = __shfl_sync(0xffffffffu, ex, j) * inv;
            int   sj = __shfl_sync(0xffffffffu, srcj, j);
            acc = fmaf(aj, H[((size_t)sj*96 + k)*96 + hh*32 + lane], acc);
        }
        val += acc + bias[hh*32 + lane];
    }
    val *= (1.f/3.f);
    int ob = k / 24, ot = k % 24;        // reference's reshape scramble
    size_t o = (size_t)((ob*TT + ot)*NN + n)*FF + gat*32 + lane;
    g_spatial[o] = inp[o] + val;
}

// ---------------- attn_S = softmax(cov0 @ cov0^T, axis=2) -- stays fp32 ------
__global__ __launch_bounds__(256)
void attnS_gemm(const float* __restrict__ spatE, float* __restrict__ Sout)
{
    extern __shared__ float sm2[];
    float* At = sm2;            // [64][97]
    float* Bt = sm2 + 64*97;    // [64][97]
    int b = blockIdx.z;
    int i0 = blockIdx.y * 64, j0 = blockIdx.x * 64;
    const float* cov = spatE + (size_t)b*TT*NN*FF;   // t = 0 slice
    int tid = threadIdx.x;       // 256
    #pragma unroll
    for (int i = 0; i < 6; ++i) {
        int idx = tid + i*256;   // < 1536
        int r = idx / 24, c4 = idx % 24;
        float4 v = *reinterpret_cast<const float4*>(cov + (i0 + r)*96 + c4*4);
        At[r*97 + c4*4+0] = v.x; At[r*97 + c4*4+1] = v.y;
        At[r*97 + c4*4+2] = v.z; At[r*97 + c4*4+3] = v.w;
        float4 w = *reinterpret_cast<const float4*>(cov + (j0 + r)*96 + c4*4);
        Bt[r*97 + c4*4+0] = w.x; Bt[r*97 + c4*4+1] = w.y;
        Bt[r*97 + c4*4+2] = w.z; Bt[r*97 + c4*4+3] = w.w;
    }
    __syncthreads();
    int tx = tid & 15, ty = tid >> 4;
    float acc[4][4];
    #pragma unroll
    for (int u = 0; u < 4; ++u)
        #pragma unroll
        for (int v = 0; v < 4; ++v) acc[u][v] = 0.f;
    #pragma unroll 8
    for (int f = 0; f < 96; ++f) {
        float a[4], bb[4];
        #pragma unroll
        for (int u = 0; u < 4; ++u) a[u] = At[(ty*4+u)*97 + f];
        #pragma unroll
        for (int v = 0; v < 4; ++v) bb[v] = Bt[(tx*4+v)*97 + f];
        #pragma unroll
        for (int u = 0; u < 4; ++u)
            #pragma unroll
            for (int v = 0; v < 4; ++v) acc[u][v] = fmaf(a[u], bb[v], acc[u][v]);
    }
    #pragma unroll
    for (int u = 0; u < 4; ++u) {
        float4 o = make_float4(acc[u][0], acc[u][1], acc[u][2], acc[u][3]);
        *reinterpret_cast<float4*>(Sout + ((size_t)b*NN + i0 + ty*4 + u)*NN + j0 + tx*4) = o;
    }
}

__global__ void rowsoftmax1024(float* __restrict__ S)
{
    int row = blockIdx.x;
    float* p = S + (size_t)row * 1024;
    int tid = threadIdx.x;   // 256
    float v[4];
    float m = -1e30f;
    #pragma unroll
    for (int q = 0; q < 4; ++q) { v[q] = p[tid + q*256]; m = fmaxf(m, v[q]); }
    __shared__ float red[8];
    __shared__ float red2[8];
    for (int o = 16; o >= 1; o >>= 1) m = fmaxf(m, __shfl_xor_sync(0xffffffffu, m, o));
    if ((tid & 31) == 0) red[tid >> 5] = m;
    __syncthreads();
    float mm = red[0];
    #pragma unroll
    for (int w = 1; w < 8; ++w) mm = fmaxf(mm, red[w]);
    float s = 0.f;
    #pragma unroll
    for (int q = 0; q < 4; ++q) { v[q] = expf(v[q] - mm); s += v[q]; }
    for (int o = 16; o >= 1; o >>= 1) s += __shfl_xor_sync(0xffffffffu, s, o);
    if ((tid & 31) == 0) red2[tid >> 5] = s;
    __syncthreads();
    float ss = 0.f;
    #pragma unroll
    for (int w = 0; w < 8; ++w) ss += red2[w];
    float inv = 1.f / ss;
    #pragma unroll
    for (int q = 0; q < 4; ++q) p[tid + q*256] = v[q] * inv;
}

// ---------------- attn_T = softmax(covT @ covT^T, axis=1) --------------------
__global__ void attnT_kernel(const float* __restrict__ tempE)
{
    __shared__ float cov[24][96];
    __shared__ float s[24][25];
    __shared__ float colmax[24], colsum[24];
    int b = blockIdx.x;
    int j = threadIdx.x, i = threadIdx.y;
    int tid = i*24 + j;
    for (int q = tid; q < 2304; q += 576) {
        int t = q / 96, f = q % 96;
        cov[t][f] = tempE[((b*TT + t)*NN)*FF + f];   // n = 0 slice
    }
    __syncthreads();
    float acc = 0.f;
    #pragma unroll
    for (int f = 0; f < 96; ++f) acc = fmaf(cov[i][f], cov[j][f], acc);
    s[i][j] = acc;
    __syncthreads();
    if (i == 0) {
        float m = -1e30f;
        for (int t = 0; t < 24; ++t) m = fmaxf(m, s[t][j]);
        colmax[j] = m;
    }
    __syncthreads();
    float e = expf(acc - colmax[j]);
    s[i][j] = e;
    __syncthreads();
    if (i == 0) {
        float sm0 = 0.f;
        for (int t = 0; t < 24; ++t) sm0 += s[t][j];
        colsum[j] = sm0;
    }
    __syncthreads();
    g_attnT[(b*TT + i)*TT + j] = e / colsum[j];
}

// ---------------- temporal branch: per (b,n), all in smem --------------------
__global__ void temporal_kernel(const float* __restrict__ input)
{
    __shared__ float hgs[2304];
    __shared__ float xts[2304];
    __shared__ float xgs[2304];
    __shared__ float alph[2304];
    __shared__ float ats[576];
    __shared__ float elgs[96], ergs[96];
    int r = blockIdx.x;              // r = b*N + n
    int b = r >> 10, n = r & 1023;
    int tid = threadIdx.x;           // 256
    for (int q = tid; q < 2304; q += 256) hgs[q] = g_hg[(size_t)r*2304 + q];
    for (int q = tid; q < 2304; q += 256) {
        int t = q / 96, f = q % 96;
        xts[q] = input[((b*TT + t)*NN + n)*FF + f];
    }
    if (tid < 96) { elgs[tid] = g_elg[r*96 + tid]; ergs[tid] = g_erg[r*96 + tid]; }
    for (int q = tid; q < 576; q += 256) ats[q] = g_attnT[(n & 3)*576 + q]; // idx = r%B = n%4
    __syncthreads();
    if (tid < 96) {                  // softmax over j for (i,g)
        int i = tid >> 2, g = tid & 3;
        float eli = elgs[i*4 + g];
        float ev[24];
        float m = -1e30f;
        #pragma unroll
        for (int j = 0; j < 24; ++j) {
            float x = eli + ergs[j*4 + g];
            x = (x >= 0.f) ? x : 0.2f*x;
            ev[j] = x;
            m = fmaxf(m, x);
        }
        float s = 0.f;
        #pragma unroll
        for (int j = 0; j < 24; ++j) { ev[j] = expf(ev[j] - m); s += ev[j]; }
        float inv = 1.f / s;
        #pragma unroll
        for (int j = 0; j < 24; ++j) alph[tid*24 + j] = ev[j]*inv;
    }
    __syncthreads();
    for (int q = tid; q < 2304; q += 256) {   // xg = alpha @ hg
        int i = q / 96, rem = q % 96, g = rem / 24, d = rem % 24;
        float acc = 0.f;
        #pragma unroll
        for (int j = 0; j < 24; ++j)
            acc = fmaf(alph[(i*4+g)*24 + j], hgs[j*96 + g*24 + d], acc);
        xgs[q] = acc;
    }
    __syncthreads();
    for (int q = tid; q < 2304; q += 256) {   // emb gate + residual
        int i = q / 96, f = q % 96;
        float emb = 0.f;
        #pragma unroll
        for (int j = 0; j < 24; ++j) emb = fmaf(ats[i*24 + j], xts[j*96 + f], emb);
        float sg = 1.f / (1.f + expf(-emb));
        g_temporal[(size_t)((b*TT + i)*NN + n)*FF + f] = xts[q] + xgs[q]*sg;
    }
}

// ---------------- fusion (tensor-core): z = sigmoid([sp,tp]@Wf + bf) ---------
// out = z*sp + (1-z)*tp + input.  128 rows/block, 256 threads.
__global__ __launch_bounds__(256)
void fusion_tc(const float* __restrict__ input, const float* __restrict__ Wf,
               const float* __restrict__ bf, float* __restrict__ outp)
{
    extern __shared__ float sm[];
    float*    Xsp = sm;                                  // [128][100] fp32
    float*    Xtp = sm + 128*100;                        // [128][100] fp32
    uint32_t* Ws  = (uint32_t*)(sm + 2*128*100);         // [192][104] tf32

    const int tid = threadIdx.x;
    const int row0 = blockIdx.x * 128;

    for (int i = tid; i < 192*24; i += 256) {
        int k = i / 24, c4 = i % 24;
        float4 v = reinterpret_cast<const float4*>(Wf)[i];
        *reinterpret_cast<uint4*>(&Ws[k*104 + c4*4]) =
            make_uint4(f2tf32(v.x), f2tf32(v.y), f2tf32(v.z), f2tf32(v.w));
    }
    for (int i = tid; i < 3072; i += 256) {
        int r = i / 24, c4 = i % 24;
        size_t off = (size_t)(row0 + r)*96 + c4*4;
        *reinterpret_cast<float4*>(&Xsp[r*100 + c4*4]) = *reinterpret_cast<const float4*>(g_spatial + off);
        *reinterpret_cast<float4*>(&Xtp[r*100 + c4*4]) = *reinterpret_cast<const float4*>(g_temporal + off);
    }
    __syncthreads();

    const int lane = tid & 31, w = tid >> 5;
    const int g = lane >> 2, tig = lane & 3;
    const int r0 = w * 16;

    float acc[12][4];
    #pragma unroll
    for (int nt = 0; nt < 12; ++nt)
        #pragma unroll
        for (int q = 0; q < 4; ++q) acc[nt][q] = 0.f;

    #pragma unroll
    for (int ks = 0; ks < 12; ++ks) {           // spatial half (Wf rows 0..95)
        int k0 = ks * 8;
        uint32_t a[4];
        a[0] = f2tf32(Xsp[(r0+g  )*100 + k0 + tig    ]);
        a[1] = f2tf32(Xsp[(r0+g+8)*100 + k0 + tig    ]);
        a[2] = f2tf32(Xsp[(r0+g  )*100 + k0 + tig + 4]);
        a[3] = f2tf32(Xsp[(r0+g+8)*100 + k0 + tig + 4]);
        #pragma unroll
        for (int nt = 0; nt < 12; ++nt) {
            uint32_t b0 = Ws[(k0+tig  )*104 + nt*8 + g];
            uint32_t b1 = Ws[(k0+tig+4)*104 + nt*8 + g];
            mma_tf32(acc[nt], a, b0, b1);
        }
    }
    #pragma unroll
    for (int ks = 0; ks < 12; ++ks) {           // temporal half (Wf rows 96..191)
        int k0 = ks * 8;
        uint32_t a[4];
        a[0] = f2tf32(Xtp[(r0+g  )*100 + k0 + tig    ]);
        a[1] = f2tf32(Xtp[(r0+g+8)*100 + k0 + tig    ]);
        a[2] = f2tf32(Xtp[(r0+g  )*100 + k0 + tig + 4]);
        a[3] = f2tf32(Xtp[(r0+g+8)*100 + k0 + tig + 4]);
        #pragma unroll
        for (int nt = 0; nt < 12; ++nt) {
            uint32_t b0 = Ws[(96+k0+tig  )*104 + nt*8 + g];
            uint32_t b1 = Ws[(96+k0+tig+4)*104 + nt*8 + g];
            mma_tf32(acc[nt], a, b0, b1);
        }
    }

    const int gr0 = row0 + r0 + g, gr1 = gr0 + 8;
    const int rl0 = r0 + g, rl1 = rl0 + 8;
    #pragma unroll
    for (int nt = 0; nt < 12; ++nt) {
        int col = nt*8 + 2*tig;
        float b0v = bf[col], b1v = bf[col+1];
        float2 in0 = *reinterpret_cast<const float2*>(input + (size_t)gr0*96 + col);
        float2 in1 = *reinterpret_cast<const float2*>(input + (size_t)gr1*96 + col);
        float z00 = 1.f/(1.f+expf(-(acc[nt][0] + b0v)));
        float z01 = 1.f/(1.f+expf(-(acc[nt][1] + b1v)));
        float z10 = 1.f/(1.f+expf(-(acc[nt][2] + b0v)));
        float z11 = 1.f/(1.f+expf(-(acc[nt][3] + b1v)));
        float sp00 = Xsp[rl0*100 + col], sp01 = Xsp[rl0*100 + col + 1];
        float sp10 = Xsp[rl1*100 + col], sp11 = Xsp[rl1*100 + col + 1];
        float tp00 = Xtp[rl0*100 + col], tp01 = Xtp[rl0*100 + col + 1];
        float tp10 = Xtp[rl1*100 + col], tp11 = Xtp[rl1*100 + col + 1];
        float2 o0 = make_float2(z00*sp00 + (1.f-z00)*tp00 + in0.x,
                                z01*sp01 + (1.f-z01)*tp01 + in0.y);
        float2 o1 = make_float2(z10*sp10 + (1.f-z10)*tp10 + in1.x,
                                z11*sp11 + (1.f-z11)*tp11 + in1.y);
        *reinterpret_cast<float2*>(outp + (size_t)gr0*96 + col) = o0;
        *reinterpret_cast<float2*>(outp + (size_t)gr1*96 + col) = o1;
    }
}

extern "C" void kernel_launch(void* const* d_in, const int* in_sizes, int n_in,
                              void* d_out, int out_size)
{
    const float* input = (const float*)d_in[0];
    const float* spatE = (const float*)d_in[1];
    const float* tempE = (const float*)d_in[2];
    const int*   s0 = (const int*)d_in[3];
    const int*   s1 = (const int*)d_in[5];
    const int*   s2 = (const int*)d_in[7];
    const float* W_d = (const float*)d_in[9];
    const float* al_d = (const float*)d_in[10];
    const float* ar_d = (const float*)d_in[11];
    const float* b_d = (const float*)d_in[12];
    const float* W_m = (const float*)d_in[13];
    const float* al_m = (const float*)d_in[14];
    const float* ar_m = (const float*)d_in[15];
    const float* b_m = (const float*)d_in[16];
    const float* W_s = (const float*)d_in[17];
    const float* al_s = (const float*)d_in[18];
    const float* ar_s = (const float*)d_in[19];
    const float* b_s = (const float*)d_in[20];
    const float* Wg  = (const float*)d_in[21];
    const float* agl = (const float*)d_in[22];
    const float* agr = (const float*)d_in[23];
    const float* Wf  = (const float*)d_in[24];
    const float* bf  = (const float*)d_in[25];
    float* out   = (float*)d_out;
    float* attnS = out + (size_t)RR*96;   // out (B,T,N,F) then attn_S (B,N,N)

    const int GTC_SMEM = (128*100 + 96*104) * 4;           //  91,136 B
    const int FUS_SMEM = (2*128*100 + 192*104) * 4;        // 182,272 B
    const int ATS_SMEM = (2*64*97) * 4;                    //  49,664 B
    static int attrs_set = 0;
    if (!attrs_set) {
        cudaFuncSetAttribute(gemm_tc<3,0>, cudaFuncAttributeMaxDynamicSharedMemorySize, GTC_SMEM);
        cudaFuncSetAttribute(gemm_tc<4,1>, cudaFuncAttributeMaxDynamicSharedMemorySize, GTC_SMEM);
        cudaFuncSetAttribute(fusion_tc,    cudaFuncAttributeMaxDynamicSharedMemorySize, FUS_SMEM);
        cudaFuncSetAttribute(attnS_gemm,   cudaFuncAttributeMaxDynamicSharedMemorySize, ATS_SMEM);
        attrs_set = 1;
    }

    // spatial GATs: one fused tensor-core GEMM launch (grid.y = gat)
    gemm_tc<3,0><<<dim3(RGRID,3), 256, GTC_SMEM>>>(input, spatE,
        W_d, W_m, W_s, al_d, al_m, al_s, ar_d, ar_m, ar_s);
    // temporal projection
    gemm_tc<4,1><<<dim3(RGRID,1), 256, GTC_SMEM>>>(input, input,
        Wg, Wg, Wg, agl, agl, agl, agr, agr, agr);

    gat_agg<<<dim3(RR/4,3), 128>>>(s0, s1, s2, b_d, b_m, b_s, input);

    // attn_S (second output) — fp32 for output precision
    attnS_gemm<<<dim3(16,16,4), 256, ATS_SMEM>>>(spatE, attnS);
    rowsoftmax1024<<<4096, 256>>>(attnS);

    // attn_T (tiny) + temporal branch
    attnT_kernel<<<4, dim3(24,24)>>>(tempE);
    temporal_kernel<<<4096, 256>>>(input);

    // fusion
    fusion_tc<<<RGRID, 256, FUS_SMEM>>>(input, Wf, bf, out);
}

// round 9
// speedup vs baseline: 2.5351x; 1.0838x over previous
#include <cuda_runtime.h>
#include <math.h>
#include <stdint.h>

#define NN 1024
#define BB 4
#define TT 24
#define FF 96
#define RR (NN*96)       // 98304 rows (== B*T*N)
#define RGRID (RR/128)   // 768

// ---------------- scratch (device globals; no allocs allowed) ----------------
__device__ float g_h3[3*(size_t)RR*96];   // spatial GAT h, per gat
__device__ float g_el3[3*RR*3];
__device__ float g_er3[3*RR*3];
__device__ float g_hg[(size_t)RR*96];     // temporal hg, row = (b*N+n)*24+t
__device__ float g_elg[RR*4];
__device__ float g_erg[RR*4];
__device__ float g_spatial[(size_t)RR*96];
__device__ float g_temporal[(size_t)RR*96];
__device__ float g_attnT[BB*TT*TT];

// ---------------- tf32 helpers ----------------
__device__ __forceinline__ uint32_t f2tf32(float x) {
    uint32_t r; asm("cvt.rna.tf32.f32 %0, %1;" : "=r"(r) : "f"(x)); return r;
}
__device__ __forceinline__ void mma_tf32(float* c, const uint32_t* a, uint32_t b0, uint32_t b1) {
    asm volatile("mma.sync.aligned.m16n8k8.row.col.f32.tf32.tf32.f32 "
        "{%0,%1,%2,%3}, {%4,%5,%6,%7}, {%8,%9}, {%0,%1,%2,%3};"
        : "+f"(c[0]), "+f"(c[1]), "+f"(c[2]), "+f"(c[3])
        : "r"(a[0]), "r"(a[1]), "r"(a[2]), "r"(a[3]), "r"(b0), "r"(b1));
}

// =============== spatial GEMM: 128 rows x 96 cols, ALL 3 GATs per block ======
// row = n*96 + k (k = t*B+b), x = input + spatial_emb. A-frags tf32'd once.
__global__ __launch_bounds__(256)
void gemm_tc_sp(const float* __restrict__ X, const float* __restrict__ Emb,
                const float* __restrict__ W0, const float* __restrict__ W1, const float* __restrict__ W2,
                const float* __restrict__ al0, const float* __restrict__ al1, const float* __restrict__ al2,
                const float* __restrict__ ar0, const float* __restrict__ ar1, const float* __restrict__ ar2)
{
    extern __shared__ float sm[];
    float*    Xs = sm;                                 // [128][100] fp32
    uint32_t* Ws = (uint32_t*)(sm + 128*100);          // 3 x [96][104] tf32

    const int tid = threadIdx.x;
    const int row0 = blockIdx.x * 128;
    const float* Wp[3]  = {W0, W1, W2};
    const float* alp[3] = {al0, al1, al2};
    const float* arp[3] = {ar0, ar1, ar2};

    // all 3 W's -> smem tf32 (pitch 104)
    for (int i = tid; i < 3*2304; i += 256) {
        int gat = i / 2304, rem = i % 2304;
        int k = rem / 24, c4 = rem % 24;
        float4 v = reinterpret_cast<const float4*>(Wp[gat])[rem];
        *reinterpret_cast<uint4*>(&Ws[gat*96*104 + k*104 + c4*4]) =
            make_uint4(f2tf32(v.x), f2tf32(v.y), f2tf32(v.z), f2tf32(v.w));
    }
    // X tile -> smem fp32 (loaded ONCE for all 3 gats)
    for (int i = tid; i < 3072; i += 256) {
        int r = i / 24, c4 = i % 24;
        int gr = row0 + r;
        int n = gr / 96, k = gr % 96;
        int b = k & 3, t = k >> 2;
        int off = ((b*TT + t)*NN + n)*FF;
        float4 v = *reinterpret_cast<const float4*>(X + off + c4*4);
        float4 e = *reinterpret_cast<const float4*>(Emb + off + c4*4);
        v.x += e.x; v.y += e.y; v.z += e.z; v.w += e.w;
        *reinterpret_cast<float4*>(&Xs[r*100 + c4*4]) = v;
    }
    __syncthreads();

    const int lane = tid & 31, w = tid >> 5;
    const int g = lane >> 2, tig = lane & 3;
    const int r0 = w * 16;
    const int gr0 = row0 + r0 + g, gr1 = gr0 + 8;

    // A fragments converted once
    uint32_t af[12][4];
    #pragma unroll
    for (int ks = 0; ks < 12; ++ks) {
        int k0 = ks * 8;
        af[ks][0] = f2tf32(Xs[(r0+g  )*100 + k0 + tig    ]);
        af[ks][1] = f2tf32(Xs[(r0+g+8)*100 + k0 + tig    ]);
        af[ks][2] = f2tf32(Xs[(r0+g  )*100 + k0 + tig + 4]);
        af[ks][3] = f2tf32(Xs[(r0+g+8)*100 + k0 + tig + 4]);
    }

    for (int gat = 0; gat < 3; ++gat) {
        const uint32_t* Wg_ = Ws + gat*96*104;
        float acc[12][4];
        #pragma unroll
        for (int nt = 0; nt < 12; ++nt)
            #pragma unroll
            for (int q = 0; q < 4; ++q) acc[nt][q] = 0.f;
        #pragma unroll
        for (int ks = 0; ks < 12; ++ks) {
            int k0 = ks * 8;
            #pragma unroll
            for (int nt = 0; nt < 12; ++nt) {
                uint32_t b0 = Wg_[(k0+tig  )*104 + nt*8 + g];
                uint32_t b1 = Wg_[(k0+tig+4)*104 + nt*8 + g];
                mma_tf32(acc[nt], af[ks], b0, b1);
            }
        }
        float* Hb = g_h3 + (size_t)gat*RR*96;
        #pragma unroll
        for (int nt = 0; nt < 12; ++nt) {
            *reinterpret_cast<float2*>(Hb + (size_t)gr0*96 + nt*8 + 2*tig) = make_float2(acc[nt][0], acc[nt][1]);
            *reinterpret_cast<float2*>(Hb + (size_t)gr1*96 + nt*8 + 2*tig) = make_float2(acc[nt][2], acc[nt][3]);
        }
        const float* al = alp[gat];
        const float* ar = arp[gat];
        #pragma unroll
        for (int h = 0; h < 3; ++h) {
            float sl0 = 0.f, sr0 = 0.f, sl1 = 0.f, sr1 = 0.f;
            #pragma unroll
            for (int q = 0; q < 4; ++q) {
                int nt = h*4 + q;
                float a0 = al[nt*8 + 2*tig], a1 = al[nt*8 + 2*tig + 1];
                float c0 = ar[nt*8 + 2*tig], c1 = ar[nt*8 + 2*tig + 1];
                sl0 += acc[nt][0]*a0 + acc[nt][1]*a1;
                sr0 += acc[nt][0]*c0 + acc[nt][1]*c1;
                sl1 += acc[nt][2]*a0 + acc[nt][3]*a1;
                sr1 += acc[nt][2]*c0 + acc[nt][3]*c1;
            }
            sl0 += __shfl_xor_sync(0xffffffffu, sl0, 1); sl0 += __shfl_xor_sync(0xffffffffu, sl0, 2);
            sr0 += __shfl_xor_sync(0xffffffffu, sr0, 1); sr0 += __shfl_xor_sync(0xffffffffu, sr0, 2);
            sl1 += __shfl_xor_sync(0xffffffffu, sl1, 1); sl1 += __shfl_xor_sync(0xffffffffu, sl1, 2);
            sr1 += __shfl_xor_sync(0xffffffffu, sr1, 1); sr1 += __shfl_xor_sync(0xffffffffu, sr1, 2);
            if (tig == 0) {
                g_el3[(size_t)gat*RR*3 + gr0*3 + h] = sl0;
                g_er3[(size_t)gat*RR*3 + gr0*3 + h] = sr0;
                g_el3[(size_t)gat*RR*3 + gr1*3 + h] = sl1;
                g_er3[(size_t)gat*RR*3 + gr1*3 + h] = sr1;
            }
        }
    }
}

// =============== temporal projection GEMM (HEADS=4, MODE1) ===================
__global__ __launch_bounds__(256)
void gemm_tc_tp(const float* __restrict__ X, const float* __restrict__ W,
                const float* __restrict__ al, const float* __restrict__ ar)
{
    extern __shared__ float sm[];
    float*    Xs = sm;                                 // [128][100]
    uint32_t* Ws = (uint32_t*)(sm + 128*100);          // [96][104]
    const int tid = threadIdx.x;
    const int row0 = blockIdx.x * 128;

    for (int i = tid; i < 2304; i += 256) {
        int k = i / 24, c4 = i % 24;
        float4 v = reinterpret_cast<const float4*>(W)[i];
        *reinterpret_cast<uint4*>(&Ws[k*104 + c4*4]) =
            make_uint4(f2tf32(v.x), f2tf32(v.y), f2tf32(v.z), f2tf32(v.w));
    }
    for (int i = tid; i < 3072; i += 256) {
        int r = i / 24, c4 = i % 24;
        int gr = row0 + r;
        int rr = gr / 24, t = gr % 24;
        int b = rr >> 10, n = rr & 1023;
        int off = ((b*TT + t)*NN + n)*FF;
        *reinterpret_cast<float4*>(&Xs[r*100 + c4*4]) = *reinterpret_cast<const float4*>(X + off + c4*4);
    }
    __syncthreads();

    const int lane = tid & 31, w = tid >> 5;
    const int g = lane >> 2, tig = lane & 3;
    const int r0 = w * 16;
    float acc[12][4];
    #pragma unroll
    for (int nt = 0; nt < 12; ++nt)
        #pragma unroll
        for (int q = 0; q < 4; ++q) acc[nt][q] = 0.f;
    #pragma unroll
    for (int ks = 0; ks < 12; ++ks) {
        int k0 = ks * 8;
        uint32_t a[4];
        a[0] = f2tf32(Xs[(r0+g  )*100 + k0 + tig    ]);
        a[1] = f2tf32(Xs[(r0+g+8)*100 + k0 + tig    ]);
        a[2] = f2tf32(Xs[(r0+g  )*100 + k0 + tig + 4]);
        a[3] = f2tf32(Xs[(r0+g+8)*100 + k0 + tig + 4]);
        #pragma unroll
        for (int nt = 0; nt < 12; ++nt) {
            uint32_t b0 = Ws[(k0+tig  )*104 + nt*8 + g];
            uint32_t b1 = Ws[(k0+tig+4)*104 + nt*8 + g];
            mma_tf32(acc[nt], a, b0, b1);
        }
    }
    const int gr0 = row0 + r0 + g, gr1 = gr0 + 8;
    #pragma unroll
    for (int nt = 0; nt < 12; ++nt) {
        *reinterpret_cast<float2*>(g_hg + (size_t)gr0*96 + nt*8 + 2*tig) = make_float2(acc[nt][0], acc[nt][1]);
        *reinterpret_cast<float2*>(g_hg + (size_t)gr1*96 + nt*8 + 2*tig) = make_float2(acc[nt][2], acc[nt][3]);
    }
    #pragma unroll
    for (int h = 0; h < 4; ++h) {
        float sl0 = 0.f, sr0 = 0.f, sl1 = 0.f, sr1 = 0.f;
        #pragma unroll
        for (int q = 0; q < 3; ++q) {
            int nt = h*3 + q;
            float a0 = al[nt*8 + 2*tig], a1 = al[nt*8 + 2*tig + 1];
            float c0 = ar[nt*8 + 2*tig], c1 = ar[nt*8 + 2*tig + 1];
            sl0 += acc[nt][0]*a0 + acc[nt][1]*a1;
            sr0 += acc[nt][0]*c0 + acc[nt][1]*c1;
            sl1 += acc[nt][2]*a0 + acc[nt][3]*a1;
            sr1 += acc[nt][2]*c0 + acc[nt][3]*c1;
        }
        sl0 += __shfl_xor_sync(0xffffffffu, sl0, 1); sl0 += __shfl_xor_sync(0xffffffffu, sl0, 2);
        sr0 += __shfl_xor_sync(0xffffffffu, sr0, 1); sr0 += __shfl_xor_sync(0xffffffffu, sr0, 2);
        sl1 += __shfl_xor_sync(0xffffffffu, sl1, 1); sl1 += __shfl_xor_sync(0xffffffffu, sl1, 2);
        sr1 += __shfl_xor_sync(0xffffffffu, sr1, 1); sr1 += __shfl_xor_sync(0xffffffffu, sr1, 2);
        if (tig == 0) {
            g_elg[gr0*4 + h] = sl0;  g_erg[gr0*4 + h] = sr0;
            g_elg[gr1*4 + h] = sl1;  g_erg[gr1*4 + h] = sr1;
        }
    }
}

// ---------------- GAT aggregation v2: one block per (n, gat) -----------------
// alphas computed once per block from contiguous el/er rows; H streamed coalesced.
__global__ __launch_bounds__(256)
void gat_agg2(const int* __restrict__ src0, const int* __restrict__ src1,
              const int* __restrict__ src2,
              const float* __restrict__ bias0, const float* __restrict__ bias1,
              const float* __restrict__ bias2,
              const float* __restrict__ inp)
{
    const int gat = blockIdx.y, n = blockIdx.x, tid = threadIdx.x;
    const int*   src  = (gat == 0) ? src0  : (gat == 1) ? src1  : src2;
    const float* bias = (gat == 0) ? bias0 : (gat == 1) ? bias1 : bias2;
    const float* H  = g_h3  + (size_t)gat*RR*96;
    const float* EL = g_el3 + (size_t)gat*RR*3;
    const float* ER = g_er3 + (size_t)gat*RR*3;

    __shared__ int   ssm[8];
    __shared__ float er_s[288];
    __shared__ float as[2304];      // [q = k*3+h][j]
    __shared__ float bsum[32];

    if (tid < 8)  ssm[tid] = src[n + tid*NN];
    if (tid < 32) bsum[tid] = bias[tid] + bias[32 + tid] + bias[64 + tid];
    for (int q = tid; q < 288; q += 256) er_s[q] = ER[n*288 + q];
    __syncthreads();

    // edge logits (leaky relu), per source j: contiguous 288-float el row
    for (int j = 0; j < 8; ++j) {
        const float* elp = EL + (size_t)ssm[j] * 288;
        for (int q = tid; q < 288; q += 256) {
            float x = elp[q] + er_s[q];
            as[q*8 + j] = (x >= 0.f) ? x : 0.2f*x;
        }
    }
    __syncthreads();
    // softmax over the 8 edges per (k,h)
    for (int q = tid; q < 288; q += 256) {
        float e[8], m = -1e30f;
        #pragma unroll
        for (int j = 0; j < 8; ++j) { e[j] = as[q*8 + j]; m = fmaxf(m, e[j]); }
        float s = 0.f;
        #pragma unroll
        for (int j = 0; j < 8; ++j) { e[j] = expf(e[j] - m); s += e[j]; }
        float inv = 1.f / (s + 1e-9f);
        #pragma unroll
        for (int j = 0; j < 8; ++j) as[q*8 + j] = e[j] * inv;
    }
    __syncthreads();

    // aggregation: thread = (d, kg); 12 k's per thread; H reads coalesced
    const int d = tid & 31, kg = tid >> 5;
    float acc[12];
    #pragma unroll
    for (int s = 0; s < 12; ++s) acc[s] = 0.f;
    for (int j = 0; j < 8; ++j) {
        const float* hb = H + (size_t)ssm[j] * 96 * 96;
        #pragma unroll
        for (int s = 0; s < 12; ++s) {
            int k = kg + 8*s;
            const float* hp = hb + k*96;
            float a0 = as[(k*3+0)*8 + j];
            float a1 = as[(k*3+1)*8 + j];
            float a2 = as[(k*3+2)*8 + j];
            acc[s] += a0*hp[d] + a1*hp[32 + d] + a2*hp[64 + d];
        }
    }
    #pragma unroll
    for (int s = 0; s < 12; ++s) {
        int k = kg + 8*s;
        float val = (acc[s] + bsum[d]) * (1.f/3.f);
        int ob = k / 24, ot = k % 24;      // reference's reshape scramble
        size_t o = (size_t)((ob*TT + ot)*NN + n)*FF + gat*32 + d;
        g_spatial[o] = inp[o] + val;
    }
}

// ---------------- attn_S = softmax(cov0 @ cov0^T, axis=2) -- fp32 ------------
__global__ __launch_bounds__(256)
void attnS_gemm(const float* __restrict__ spatE, float* __restrict__ Sout)
{
    extern __shared__ float sm2[];
    float* At = sm2;            // [64][97]
    float* Bt = sm2 + 64*97;    // [64][97]
    int b = blockIdx.z;
    int i0 = blockIdx.y * 64, j0 = blockIdx.x * 64;
    const float* cov = spatE + (size_t)b*TT*NN*FF;   // t = 0 slice
    int tid = threadIdx.x;       // 256
    #pragma unroll
    for (int i = 0; i < 6; ++i) {
        int idx = tid + i*256;   // < 1536
        int r = idx / 24, c4 = idx % 24;
        float4 v = *reinterpret_cast<const float4*>(cov + (i0 + r)*96 + c4*4);
        At[r*97 + c4*4+0] = v.x; At[r*97 + c4*4+1] = v.y;
        At[r*97 + c4*4+2] = v.z; At[r*97 + c4*4+3] = v.w;
        float4 w = *reinterpret_cast<const float4*>(cov + (j0 + r)*96 + c4*4);
        Bt[r*97 + c4*4+0] = w.x; Bt[r*97 + c4*4+1] = w.y;
        Bt[r*97 + c4*4+2] = w.z; Bt[r*97 + c4*4+3] = w.w;
    }
    __syncthreads();
    int tx = tid & 15, ty = tid >> 4;
    float acc[4][4];
    #pragma unroll
    for (int u = 0; u < 4; ++u)
        #pragma unroll
        for (int v = 0; v < 4; ++v) acc[u][v] = 0.f;
    #pragma unroll 8
    for (int f = 0; f < 96; ++f) {
        float a[4], bb[4];
        #pragma unroll
        for (int u = 0; u < 4; ++u) a[u] = At[(ty*4+u)*97 + f];
        #pragma unroll
        for (int v = 0; v < 4; ++v) bb[v] = Bt[(tx*4+v)*97 + f];
        #pragma unroll
        for (int u = 0; u < 4; ++u)
            #pragma unroll
            for (int v = 0; v < 4; ++v) acc[u][v] = fmaf(a[u], bb[v], acc[u][v]);
    }
    #pragma unroll
    for (int u = 0; u < 4; ++u) {
        float4 o = make_float4(acc[u][0], acc[u][1], acc[u][2], acc[u][3]);
        *reinterpret_cast<float4*>(Sout + ((size_t)b*NN + i0 + ty*4 + u)*NN + j0 + tx*4) = o;
    }
}

__global__ void rowsoftmax1024(float* __restrict__ S)
{
    int row = blockIdx.x;
    float* p = S + (size_t)row * 1024;
    int tid = threadIdx.x;   // 256
    float v[4];
    float m = -1e30f;
    #pragma unroll
    for (int q = 0; q < 4; ++q) { v[q] = p[tid + q*256]; m = fmaxf(m, v[q]); }
    __shared__ float red[8];
    __shared__ float red2[8];
    for (int o = 16; o >= 1; o >>= 1) m = fmaxf(m, __shfl_xor_sync(0xffffffffu, m, o));
    if ((tid & 31) == 0) red[tid >> 5] = m;
    __syncthreads();
    float mm = red[0];
    #pragma unroll
    for (int w = 1; w < 8; ++w) mm = fmaxf(mm, red[w]);
    float s = 0.f;
    #pragma unroll
    for (int q = 0; q < 4; ++q) { v[q] = expf(v[q] - mm); s += v[q]; }
    for (int o = 16; o >= 1; o >>= 1) s += __shfl_xor_sync(0xffffffffu, s, o);
    if ((tid & 31) == 0) red2[tid >> 5] = s;
    __syncthreads();
    float ss = 0.f;
    #pragma unroll
    for (int w = 0; w < 8; ++w) ss += red2[w];
    float inv = 1.f / ss;
    #pragma unroll
    for (int q = 0; q < 4; ++q) p[tid + q*256] = v[q] * inv;
}

// ---------------- attn_T = softmax(covT @ covT^T, axis=1) --------------------
__global__ void attnT_kernel(const float* __restrict__ tempE)
{
    __shared__ float cov[24][96];
    __shared__ float s[24][25];
    __shared__ float colmax[24], colsum[24];
    int b = blockIdx.x;
    int j = threadIdx.x, i = threadIdx.y;
    int tid = i*24 + j;
    for (int q = tid; q < 2304; q += 576) {
        int t = q / 96, f = q % 96;
        cov[t][f] = tempE[((b*TT + t)*NN)*FF + f];   // n = 0 slice
    }
    __syncthreads();
    float acc = 0.f;
    #pragma unroll
    for (int f = 0; f < 96; ++f) acc = fmaf(cov[i][f], cov[j][f], acc);
    s[i][j] = acc;
    __syncthreads();
    if (i == 0) {
        float m = -1e30f;
        for (int t = 0; t < 24; ++t) m = fmaxf(m, s[t][j]);
        colmax[j] = m;
    }
    __syncthreads();
    float e = expf(acc - colmax[j]);
    s[i][j] = e;
    __syncthreads();
    if (i == 0) {
        float sm0 = 0.f;
        for (int t = 0; t < 24; ++t) sm0 += s[t][j];
        colsum[j] = sm0;
    }
    __syncthreads();
    g_attnT[(b*TT + i)*TT + j] = e / colsum[j];
}

// ---------------- temporal branch v2: 288 threads, register-hoisted ----------
__global__ __launch_bounds__(288)
void temporal2(const float* __restrict__ input)
{
    __shared__ float hgs[2304];
    __shared__ float xts[2304];
    __shared__ float alph[2304];
    __shared__ float ats[576];
    __shared__ float elgs[96], ergs[96];
    int r = blockIdx.x;              // r = b*N + n
    int b = r >> 10, n = r & 1023;
    int tid = threadIdx.x;           // 288
    for (int q = tid; q < 2304; q += 288) hgs[q] = g_hg[(size_t)r*2304 + q];
    for (int q = tid; q < 2304; q += 288) {
        int t = q / 96, f = q % 96;
        xts[q] = input[((b*TT + t)*NN + n)*FF + f];
    }
    if (tid < 96) { elgs[tid] = g_elg[r*96 + tid]; ergs[tid] = g_erg[r*96 + tid]; }
    for (int q = tid; q < 576; q += 288) ats[q] = g_attnT[(n & 3)*576 + q]; // idx = r%B = n%4
    __syncthreads();
    if (tid < 96) {                  // softmax over j for (i,g)
        int i = tid >> 2, g = tid & 3;
        float eli = elgs[i*4 + g];
        float ev[24];
        float m = -1e30f;
        #pragma unroll
        for (int j = 0; j < 24; ++j) {
            float x = eli + ergs[j*4 + g];
            x = (x >= 0.f) ? x : 0.2f*x;
            ev[j] = x;
            m = fmaxf(m, x);
        }
        float s = 0.f;
        #pragma unroll
        for (int j = 0; j < 24; ++j) { ev[j] = expf(ev[j] - m); s += ev[j]; }
        float inv = 1.f / s;
        #pragma unroll
        for (int j = 0; j < 24; ++j) alph[tid*24 + j] = ev[j]*inv;
    }
    __syncthreads();

    // thread = (f, tr): f fixed -> hoist hg/xt columns into registers
    int f = tid % 96, tr = tid / 96;       // tr 0..2
    int g = f / 24;
    float hv[24], xv[24];
    #pragma unroll
    for (int j = 0; j < 24; ++j) { hv[j] = hgs[j*96 + f]; xv[j] = xts[j*96 + f]; }
    #pragma unroll
    for (int s = 0; s < 8; ++s) {
        int i = tr + 3*s;
        float xa = 0.f, ea = 0.f;
        const float* ap = &alph[(i*4 + g)*24];
        const float* tp = &ats[i*24];
        #pragma unroll
        for (int j = 0; j < 24; ++j) {
            xa = fmaf(ap[j], hv[j], xa);
            ea = fmaf(tp[j], xv[j], ea);
        }
        float sg = 1.f / (1.f + expf(-ea));
        g_temporal[(size_t)((b*TT + i)*NN + n)*FF + f] = xv[i] + xa*sg;
    }
}

// ---------------- fusion (tensor-core): z = sigmoid([sp,tp]@Wf + bf) ---------
__global__ __launch_bounds__(256)
void fusion_tc(const float* __restrict__ input, const float* __restrict__ Wf,
               const float* __restrict__ bf, float* __restrict__ outp)
{
    extern __shared__ float sm[];
    float*    Xsp = sm;                                  // [128][100] fp32
    float*    Xtp = sm + 128*100;                        // [128][100] fp32
    uint32_t* Ws  = (uint32_t*)(sm + 2*128*100);         // [192][104] tf32

    const int tid = threadIdx.x;
    const int row0 = blockIdx.x * 128;

    for (int i = tid; i < 192*24; i += 256) {
        int k = i / 24, c4 = i % 24;
        float4 v = reinterpret_cast<const float4*>(Wf)[i];
        *reinterpret_cast<uint4*>(&Ws[k*104 + c4*4]) =
            make_uint4(f2tf32(v.x), f2tf32(v.y), f2tf32(v.z), f2tf32(v.w));
    }
    for (int i = tid; i < 3072; i += 256) {
        int r = i / 24, c4 = i % 24;
        size_t off = (size_t)(row0 + r)*96 + c4*4;
        *reinterpret_cast<float4*>(&Xsp[r*100 + c4*4]) = *reinterpret_cast<const float4*>(g_spatial + off);
        *reinterpret_cast<float4*>(&Xtp[r*100 + c4*4]) = *reinterpret_cast<const float4*>(g_temporal + off);
    }
    __syncthreads();

    const int lane = tid & 31, w = tid >> 5;
    const int g = lane >> 2, tig = lane & 3;
    const int r0 = w * 16;

    float acc[12][4];
    #pragma unroll
    for (int nt = 0; nt < 12; ++nt)
        #pragma unroll
        for (int q = 0; q < 4; ++q) acc[nt][q] = 0.f;

    #pragma unroll
    for (int ks = 0; ks < 12; ++ks) {           // spatial half (Wf rows 0..95)
        int k0 = ks * 8;
        uint32_t a[4];
        a[0] = f2tf32(Xsp[(r0+g  )*100 + k0 + tig    ]);
        a[1] = f2tf32(Xsp[(r0+g+8)*100 + k0 + tig    ]);
        a[2] = f2tf32(Xsp[(r0+g  )*100 + k0 + tig + 4]);
        a[3] = f2tf32(Xsp[(r0+g+8)*100 + k0 + tig + 4]);
        #pragma unroll
        for (int nt = 0; nt < 12; ++nt) {
            uint32_t b0 = Ws[(k0+tig  )*104 + nt*8 + g];
            uint32_t b1 = Ws[(k0+tig+4)*104 + nt*8 + g];
            mma_tf32(acc[nt], a, b0, b1);
        }
    }
    #pragma unroll
    for (int ks = 0; ks < 12; ++ks) {           // temporal half (Wf rows 96..191)
        int k0 = ks * 8;
        uint32_t a[4];
        a[0] = f2tf32(Xtp[(r0+g  )*100 + k0 + tig    ]);
        a[1] = f2tf32(Xtp[(r0+g+8)*100 + k0 + tig    ]);
        a[2] = f2tf32(Xtp[(r0+g  )*100 + k0 + tig + 4]);
        a[3] = f2tf32(Xtp[(r0+g+8)*100 + k0 + tig + 4]);
        #pragma unroll
        for (int nt = 0; nt < 12; ++nt) {
            uint32_t b0 = Ws[(96+k0+tig  )*104 + nt*8 + g];
            uint32_t b1 = Ws[(96+k0+tig+4)*104 + nt*8 + g];
            mma_tf32(acc[nt], a, b0, b1);
        }
    }

    const int gr0 = row0 + r0 + g, gr1 = gr0 + 8;
    const int rl0 = r0 + g, rl1 = rl0 + 8;
    #pragma unroll
    for (int nt = 0; nt < 12; ++nt) {
        int col = nt*8 + 2*tig;
        float b0v = bf[col], b1v = bf[col+1];
        float2 in0 = *reinterpret_cast<const float2*>(input + (size_t)gr0*96 + col);
        float2 in1 = *reinterpret_cast<const float2*>(input + (size_t)gr1*96 + col);
        float z00 = 1.f/(1.f+expf(-(acc[nt][0] + b0v)));
        float z01 = 1.f/(1.f+expf(-(acc[nt][1] + b1v)));
        float z10 = 1.f/(1.f+expf(-(acc[nt][2] + b0v)));
        float z11 = 1.f/(1.f+expf(-(acc[nt][3] + b1v)));
        float sp00 = Xsp[rl0*100 + col], sp01 = Xsp[rl0*100 + col + 1];
        float sp10 = Xsp[rl1*100 + col], sp11 = Xsp[rl1*100 + col + 1];
        float tp00 = Xtp[rl0*100 + col], tp01 = Xtp[rl0*100 + col + 1];
        float tp10 = Xtp[rl1*100 + col], tp11 = Xtp[rl1*100 + col + 1];
        float2 o0 = make_float2(z00*sp00 + (1.f-z00)*tp00 + in0.x,
                                z01*sp01 + (1.f-z01)*tp01 + in0.y);
        float2 o1 = make_float2(z10*sp10 + (1.f-z10)*tp10 + in1.x,
                                z11*sp11 + (1.f-z11)*tp11 + in1.y);
        *reinterpret_cast<float2*>(outp + (size_t)gr0*96 + col) = o0;
        *reinterpret_cast<float2*>(outp + (size_t)gr1*96 + col) = o1;
    }
}

extern "C" void kernel_launch(void* const* d_in, const int* in_sizes, int n_in,
                              void* d_out, int out_size)
{
    const float* input = (const float*)d_in[0];
    const float* spatE = (const float*)d_in[1];
    const float* tempE = (const float*)d_in[2];
    const int*   s0 = (const int*)d_in[3];
    const int*   s1 = (const int*)d_in[5];
    const int*   s2 = (const int*)d_in[7];
    const float* W_d = (const float*)d_in[9];
    const float* al_d = (const float*)d_in[10];
    const float* ar_d = (const float*)d_in[11];
    const float* b_d = (const float*)d_in[12];
    const float* W_m = (const float*)d_in[13];
    const float* al_m = (const float*)d_in[14];
    const float* ar_m = (const float*)d_in[15];
    const float* b_m = (const float*)d_in[16];
    const float* W_s = (const float*)d_in[17];
    const float* al_s = (const float*)d_in[18];
    const float* ar_s = (const float*)d_in[19];
    const float* b_s = (const float*)d_in[20];
    const float* Wg  = (const float*)d_in[21];
    const float* agl = (const float*)d_in[22];
    const float* agr = (const float*)d_in[23];
    const float* Wf  = (const float*)d_in[24];
    const float* bf  = (const float*)d_in[25];
    float* out   = (float*)d_out;
    float* attnS = out + (size_t)RR*96;   // out (B,T,N,F) then attn_S (B,N,N)

    const int SP_SMEM  = (128*100 + 3*96*104) * 4;         // 171,008 B
    const int TP_SMEM  = (128*100 + 96*104) * 4;           //  91,136 B
    const int FUS_SMEM = (2*128*100 + 192*104) * 4;        // 182,272 B
    const int ATS_SMEM = (2*64*97) * 4;                    //  49,664 B
    static int attrs_set = 0;
    if (!attrs_set) {
        cudaFuncSetAttribute(gemm_tc_sp, cudaFuncAttributeMaxDynamicSharedMemorySize, SP_SMEM);
        cudaFuncSetAttribute(gemm_tc_tp, cudaFuncAttributeMaxDynamicSharedMemorySize, TP_SMEM);
        cudaFuncSetAttribute(fusion_tc,  cudaFuncAttributeMaxDynamicSharedMemorySize, FUS_SMEM);
        cudaFuncSetAttribute(attnS_gemm, cudaFuncAttributeMaxDynamicSharedMemorySize, ATS_SMEM);
        attrs_set = 1;
    }

    // spatial GATs: one block computes all 3 gats (X loaded/converted once)
    gemm_tc_sp<<<RGRID, 256, SP_SMEM>>>(input, spatE,
        W_d, W_m, W_s, al_d, al_m, al_s, ar_d, ar_m, ar_s);
    // temporal projection
    gemm_tc_tp<<<RGRID, 256, TP_SMEM>>>(input, Wg, agl, agr);

    // aggregation: block per (n, gat), coalesced H streaming
    gat_agg2<<<dim3(NN, 3), 256>>>(s0, s1, s2, b_d, b_m, b_s, input);

    // attn_S (second output) — fp32 for output precision
    attnS_gemm<<<dim3(16,16,4), 256, ATS_SMEM>>>(spatE, attnS);
    rowsoftmax1024<<<4096, 256>>>(attnS);

    // attn_T (tiny) + temporal branch
    attnT_kernel<<<4, dim3(24,24)>>>(tempE);
    temporal2<<<4096, 288>>>(input);

    // fusion
    fusion_tc<<<RGRID, 256, FUS_SMEM>>>(input, Wf, bf, out);
}

// round 11
// speedup vs baseline: 2.7577x; 1.0878x over previous
#include <cuda_runtime.h>
#include <math.h>
#include <stdint.h>

#define NN 1024
#define BB 4
#define TT 24
#define FF 96
#define RR (NN*96)       // 98304 rows (== B*T*N)
#define RGRID (RR/128)   // 768

// ---------------- scratch (device globals; no allocs allowed) ----------------
__device__ float g_h3[3*(size_t)RR*96];   // spatial GAT h, per gat
__device__ float g_el3[3*RR*3];
__device__ float g_er3[3*RR*3];
__device__ float g_hg[(size_t)RR*96];     // temporal hg, row = (b*N+n)*24+t
__device__ float g_elg[RR*4];
__device__ float g_erg[RR*4];
__device__ float g_spatial[(size_t)RR*96];
__device__ float g_temporal[(size_t)RR*96];
__device__ float g_attnT[BB*TT*TT];

// ---------------- tf32 helpers ----------------
__device__ __forceinline__ uint32_t f2tf32(float x) {
    uint32_t r; asm("cvt.rna.tf32.f32 %0, %1;" : "=r"(r) : "f"(x)); return r;
}
__device__ __forceinline__ void mma_tf32(float* c, const uint32_t* a, uint32_t b0, uint32_t b1) {
    asm volatile("mma.sync.aligned.m16n8k8.row.col.f32.tf32.tf32.f32 "
        "{%0,%1,%2,%3}, {%4,%5,%6,%7}, {%8,%9}, {%0,%1,%2,%3};"
        : "+f"(c[0]), "+f"(c[1]), "+f"(c[2]), "+f"(c[3])
        : "r"(a[0]), "r"(a[1]), "r"(a[2]), "r"(a[3]), "r"(b0), "r"(b1));
}

// =============== spatial GEMM: 128 rows x 96 cols, ALL 3 GATs per block ======
__global__ __launch_bounds__(256)
void gemm_tc_sp(const float* __restrict__ X, const float* __restrict__ Emb,
                const float* __restrict__ W0, const float* __restrict__ W1, const float* __restrict__ W2,
                const float* __restrict__ al0, const float* __restrict__ al1, const float* __restrict__ al2,
                const float* __restrict__ ar0, const float* __restrict__ ar1, const float* __restrict__ ar2)
{
    extern __shared__ float sm[];
    float*    Xs = sm;                                 // [128][100] fp32
    uint32_t* Ws = (uint32_t*)(sm + 128*100);          // 3 x [96][104] tf32

    const int tid = threadIdx.x;
    const int row0 = blockIdx.x * 128;
    const float* Wp[3]  = {W0, W1, W2};
    const float* alp[3] = {al0, al1, al2};
    const float* arp[3] = {ar0, ar1, ar2};

    for (int i = tid; i < 3*2304; i += 256) {
        int gat = i / 2304, rem = i % 2304;
        int k = rem / 24, c4 = rem % 24;
        float4 v = reinterpret_cast<const float4*>(Wp[gat])[rem];
        *reinterpret_cast<uint4*>(&Ws[gat*96*104 + k*104 + c4*4]) =
            make_uint4(f2tf32(v.x), f2tf32(v.y), f2tf32(v.z), f2tf32(v.w));
    }
    for (int i = tid; i < 3072; i += 256) {
        int r = i / 24, c4 = i % 24;
        int gr = row0 + r;
        int n = gr / 96, k = gr % 96;
        int b = k & 3, t = k >> 2;
        int off = ((b*TT + t)*NN + n)*FF;
        float4 v = *reinterpret_cast<const float4*>(X + off + c4*4);
        float4 e = *reinterpret_cast<const float4*>(Emb + off + c4*4);
        v.x += e.x; v.y += e.y; v.z += e.z; v.w += e.w;
        *reinterpret_cast<float4*>(&Xs[r*100 + c4*4]) = v;
    }
    __syncthreads();

    const int lane = tid & 31, w = tid >> 5;
    const int g = lane >> 2, tig = lane & 3;
    const int r0 = w * 16;
    const int gr0 = row0 + r0 + g, gr1 = gr0 + 8;

    uint32_t af[12][4];
    #pragma unroll
    for (int ks = 0; ks < 12; ++ks) {
        int k0 = ks * 8;
        af[ks][0] = f2tf32(Xs[(r0+g  )*100 + k0 + tig    ]);
        af[ks][1] = f2tf32(Xs[(r0+g+8)*100 + k0 + tig    ]);
        af[ks][2] = f2tf32(Xs[(r0+g  )*100 + k0 + tig + 4]);
        af[ks][3] = f2tf32(Xs[(r0+g+8)*100 + k0 + tig + 4]);
    }

    for (int gat = 0; gat < 3; ++gat) {
        const uint32_t* Wg_ = Ws + gat*96*104;
        float acc[12][4];
        #pragma unroll
        for (int nt = 0; nt < 12; ++nt)
            #pragma unroll
            for (int q = 0; q < 4; ++q) acc[nt][q] = 0.f;
        #pragma unroll
        for (int ks = 0; ks < 12; ++ks) {
            int k0 = ks * 8;
            #pragma unroll
            for (int nt = 0; nt < 12; ++nt) {
                uint32_t b0 = Wg_[(k0+tig  )*104 + nt*8 + g];
                uint32_t b1 = Wg_[(k0+tig+4)*104 + nt*8 + g];
                mma_tf32(acc[nt], af[ks], b0, b1);
            }
        }
        float* Hb = g_h3 + (size_t)gat*RR*96;
        #pragma unroll
        for (int nt = 0; nt < 12; ++nt) {
            *reinterpret_cast<float2*>(Hb + (size_t)gr0*96 + nt*8 + 2*tig) = make_float2(acc[nt][0], acc[nt][1]);
            *reinterpret_cast<float2*>(Hb + (size_t)gr1*96 + nt*8 + 2*tig) = make_float2(acc[nt][2], acc[nt][3]);
        }
        const float* al = alp[gat];
        const float* ar = arp[gat];
        #pragma unroll
        for (int h = 0; h < 3; ++h) {
            float sl0 = 0.f, sr0 = 0.f, sl1 = 0.f, sr1 = 0.f;
            #pragma unroll
            for (int q = 0; q < 4; ++q) {
                int nt = h*4 + q;
                float a0 = al[nt*8 + 2*tig], a1 = al[nt*8 + 2*tig + 1];
                float c0 = ar[nt*8 + 2*tig], c1 = ar[nt*8 + 2*tig + 1];
                sl0 += acc[nt][0]*a0 + acc[nt][1]*a1;
                sr0 += acc[nt][0]*c0 + acc[nt][1]*c1;
                sl1 += acc[nt][2]*a0 + acc[nt][3]*a1;
                sr1 += acc[nt][2]*c0 + acc[nt][3]*c1;
            }
            sl0 += __shfl_xor_sync(0xffffffffu, sl0, 1); sl0 += __shfl_xor_sync(0xffffffffu, sl0, 2);
            sr0 += __shfl_xor_sync(0xffffffffu, sr0, 1); sr0 += __shfl_xor_sync(0xffffffffu, sr0, 2);
            sl1 += __shfl_xor_sync(0xffffffffu, sl1, 1); sl1 += __shfl_xor_sync(0xffffffffu, sl1, 2);
            sr1 += __shfl_xor_sync(0xffffffffu, sr1, 1); sr1 += __shfl_xor_sync(0xffffffffu, sr1, 2);
            if (tig == 0) {
                g_el3[(size_t)gat*RR*3 + gr0*3 + h] = sl0;
                g_er3[(size_t)gat*RR*3 + gr0*3 + h] = sr0;
                g_el3[(size_t)gat*RR*3 + gr1*3 + h] = sl1;
                g_er3[(size_t)gat*RR*3 + gr1*3 + h] = sr1;
            }
        }
    }
}

// =============== temporal projection GEMM (HEADS=4) ==========================
__global__ __launch_bounds__(256)
void gemm_tc_tp(const float* __restrict__ X, const float* __restrict__ W,
                const float* __restrict__ al, const float* __restrict__ ar)
{
    extern __shared__ float sm[];
    float*    Xs = sm;                                 // [128][100]
    uint32_t* Ws = (uint32_t*)(sm + 128*100);          // [96][104]
    const int tid = threadIdx.x;
    const int row0 = blockIdx.x * 128;

    for (int i = tid; i < 2304; i += 256) {
        int k = i / 24, c4 = i % 24;
        float4 v = reinterpret_cast<const float4*>(W)[i];
        *reinterpret_cast<uint4*>(&Ws[k*104 + c4*4]) =
            make_uint4(f2tf32(v.x), f2tf32(v.y), f2tf32(v.z), f2tf32(v.w));
    }
    for (int i = tid; i < 3072; i += 256) {
        int r = i / 24, c4 = i % 24;
        int gr = row0 + r;
        int rr = gr / 24, t = gr % 24;
        int b = rr >> 10, n = rr & 1023;
        int off = ((b*TT + t)*NN + n)*FF;
        *reinterpret_cast<float4*>(&Xs[r*100 + c4*4]) = *reinterpret_cast<const float4*>(X + off + c4*4);
    }
    __syncthreads();

    const int lane = tid & 31, w = tid >> 5;
    const int g = lane >> 2, tig = lane & 3;
    const int r0 = w * 16;
    float acc[12][4];
    #pragma unroll
    for (int nt = 0; nt < 12; ++nt)
        #pragma unroll
        for (int q = 0; q < 4; ++q) acc[nt][q] = 0.f;
    #pragma unroll
    for (int ks = 0; ks < 12; ++ks) {
        int k0 = ks * 8;
        uint32_t a[4];
        a[0] = f2tf32(Xs[(r0+g  )*100 + k0 + tig    ]);
        a[1] = f2tf32(Xs[(r0+g+8)*100 + k0 + tig    ]);
        a[2] = f2tf32(Xs[(r0+g  )*100 + k0 + tig + 4]);
        a[3] = f2tf32(Xs[(r0+g+8)*100 + k0 + tig + 4]);
        #pragma unroll
        for (int nt = 0; nt < 12; ++nt) {
            uint32_t b0 = Ws[(k0+tig  )*104 + nt*8 + g];
            uint32_t b1 = Ws[(k0+tig+4)*104 + nt*8 + g];
            mma_tf32(acc[nt], a, b0, b1);
        }
    }
    const int gr0 = row0 + r0 + g, gr1 = gr0 + 8;
    #pragma unroll
    for (int nt = 0; nt < 12; ++nt) {
        *reinterpret_cast<float2*>(g_hg + (size_t)gr0*96 + nt*8 + 2*tig) = make_float2(acc[nt][0], acc[nt][1]);
        *reinterpret_cast<float2*>(g_hg + (size_t)gr1*96 + nt*8 + 2*tig) = make_float2(acc[nt][2], acc[nt][3]);
    }
    #pragma unroll
    for (int h = 0; h < 4; ++h) {
        float sl0 = 0.f, sr0 = 0.f, sl1 = 0.f, sr1 = 0.f;
        #pragma unroll
        for (int q = 0; q < 3; ++q) {
            int nt = h*3 + q;
            float a0 = al[nt*8 + 2*tig], a1 = al[nt*8 + 2*tig + 1];
            float c0 = ar[nt*8 + 2*tig], c1 = ar[nt*8 + 2*tig + 1];
            sl0 += acc[nt][0]*a0 + acc[nt][1]*a1;
            sr0 += acc[nt][0]*c0 + acc[nt][1]*c1;
            sl1 += acc[nt][2]*a0 + acc[nt][3]*a1;
            sr1 += acc[nt][2]*c0 + acc[nt][3]*c1;
        }
        sl0 += __shfl_xor_sync(0xffffffffu, sl0, 1); sl0 += __shfl_xor_sync(0xffffffffu, sl0, 2);
        sr0 += __shfl_xor_sync(0xffffffffu, sr0, 1); sr0 += __shfl_xor_sync(0xffffffffu, sr0, 2);
        sl1 += __shfl_xor_sync(0xffffffffu, sl1, 1); sl1 += __shfl_xor_sync(0xffffffffu, sl1, 2);
        sr1 += __shfl_xor_sync(0xffffffffu, sr1, 1); sr1 += __shfl_xor_sync(0xffffffffu, sr1, 2);
        if (tig == 0) {
            g_elg[gr0*4 + h] = sl0;  g_erg[gr0*4 + h] = sr0;
            g_elg[gr1*4 + h] = sl1;  g_erg[gr1*4 + h] = sr1;
        }
    }
}

// ---------------- GAT aggregation v2: one block per (n, gat) -----------------
__global__ __launch_bounds__(256)
void gat_agg2(const int* __restrict__ src0, const int* __restrict__ src1,
              const int* __restrict__ src2,
              const float* __restrict__ bias0, const float* __restrict__ bias1,
              const float* __restrict__ bias2,
              const float* __restrict__ inp)
{
    const int gat = blockIdx.y, n = blockIdx.x, tid = threadIdx.x;
    const int*   src  = (gat == 0) ? src0  : (gat == 1) ? src1  : src2;
    const float* bias = (gat == 0) ? bias0 : (gat == 1) ? bias1 : bias2;
    const float* H  = g_h3  + (size_t)gat*RR*96;
    const float* EL = g_el3 + (size_t)gat*RR*3;
    const float* ER = g_er3 + (size_t)gat*RR*3;

    __shared__ int   ssm[8];
    __shared__ float er_s[288];
    __shared__ float as[2304];      // [q = k*3+h][j]
    __shared__ float bsum[32];

    if (tid < 8)  ssm[tid] = src[n + tid*NN];
    if (tid < 32) bsum[tid] = bias[tid] + bias[32 + tid] + bias[64 + tid];
    for (int q = tid; q < 288; q += 256) er_s[q] = ER[n*288 + q];
    __syncthreads();

    for (int j = 0; j < 8; ++j) {
        const float* elp = EL + (size_t)ssm[j] * 288;
        for (int q = tid; q < 288; q += 256) {
            float x = elp[q] + er_s[q];
            as[q*8 + j] = (x >= 0.f) ? x : 0.2f*x;
        }
    }
    __syncthreads();
    for (int q = tid; q < 288; q += 256) {
        float e[8], m = -1e30f;
        #pragma unroll
        for (int j = 0; j < 8; ++j) { e[j] = as[q*8 + j]; m = fmaxf(m, e[j]); }
        float s = 0.f;
        #pragma unroll
        for (int j = 0; j < 8; ++j) { e[j] = expf(e[j] - m); s += e[j]; }
        float inv = 1.f / (s + 1e-9f);
        #pragma unroll
        for (int j = 0; j < 8; ++j) as[q*8 + j] = e[j] * inv;
    }
    __syncthreads();

    const int d = tid & 31, kg = tid >> 5;
    float acc[12];
    #pragma unroll
    for (int s = 0; s < 12; ++s) acc[s] = 0.f;
    for (int j = 0; j < 8; ++j) {
        const float* hb = H + (size_t)ssm[j] * 96 * 96;
        #pragma unroll
        for (int s = 0; s < 12; ++s) {
            int k = kg + 8*s;
            const float* hp = hb + k*96;
            float a0 = as[(k*3+0)*8 + j];
            float a1 = as[(k*3+1)*8 + j];
            float a2 = as[(k*3+2)*8 + j];
            acc[s] += a0*hp[d] + a1*hp[32 + d] + a2*hp[64 + d];
        }
    }
    #pragma unroll
    for (int s = 0; s < 12; ++s) {
        int k = kg + 8*s;
        float val = (acc[s] + bsum[d]) * (1.f/3.f);
        int ob = k / 24, ot = k % 24;      // reference's reshape scramble
        size_t o = (size_t)((ob*TT + ot)*NN + n)*FF + gat*32 + d;
        g_spatial[o] = inp[o] + val;
    }
}

// ---------------- attn_S = softmax(cov0 @ cov0^T, axis=2) -- fp32 ------------
__global__ __launch_bounds__(256)
void attnS_gemm(const float* __restrict__ spatE, float* __restrict__ Sout)
{
    extern __shared__ float sm2[];
    float* At = sm2;            // [64][97]
    float* Bt = sm2 + 64*97;    // [64][97]
    int b = blockIdx.z;
    int i0 = blockIdx.y * 64, j0 = blockIdx.x * 64;
    const float* cov = spatE + (size_t)b*TT*NN*FF;   // t = 0 slice
    int tid = threadIdx.x;       // 256
    #pragma unroll
    for (int i = 0; i < 6; ++i) {
        int idx = tid + i*256;   // < 1536
        int r = idx / 24, c4 = idx % 24;
        float4 v = *reinterpret_cast<const float4*>(cov + (i0 + r)*96 + c4*4);
        At[r*97 + c4*4+0] = v.x; At[r*97 + c4*4+1] = v.y;
        At[r*97 + c4*4+2] = v.z; At[r*97 + c4*4+3] = v.w;
        float4 w = *reinterpret_cast<const float4*>(cov + (j0 + r)*96 + c4*4);
        Bt[r*97 + c4*4+0] = w.x; Bt[r*97 + c4*4+1] = w.y;
        Bt[r*97 + c4*4+2] = w.z; Bt[r*97 + c4*4+3] = w.w;
    }
    __syncthreads();
    int tx = tid & 15, ty = tid >> 4;
    float acc[4][4];
    #pragma unroll
    for (int u = 0; u < 4; ++u)
        #pragma unroll
        for (int v = 0; v < 4; ++v) acc[u][v] = 0.f;
    #pragma unroll 8
    for (int f = 0; f < 96; ++f) {
        float a[4], bb[4];
        #pragma unroll
        for (int u = 0; u < 4; ++u) a[u] = At[(ty*4+u)*97 + f];
        #pragma unroll
        for (int v = 0; v < 4; ++v) bb[v] = Bt[(tx*4+v)*97 + f];
        #pragma unroll
        for (int u = 0; u < 4; ++u)
            #pragma unroll
            for (int v = 0; v < 4; ++v) acc[u][v] = fmaf(a[u], bb[v], acc[u][v]);
    }
    #pragma unroll
    for (int u = 0; u < 4; ++u) {
        float4 o = make_float4(acc[u][0], acc[u][1], acc[u][2], acc[u][3]);
        *reinterpret_cast<float4*>(Sout + ((size_t)b*NN + i0 + ty*4 + u)*NN + j0 + tx*4) = o;
    }
}

__global__ void rowsoftmax1024(float* __restrict__ S)
{
    int row = blockIdx.x;
    float* p = S + (size_t)row * 1024;
    int tid = threadIdx.x;   // 256
    float v[4];
    float m = -1e30f;
    #pragma unroll
    for (int q = 0; q < 4; ++q) { v[q] = p[tid + q*256]; m = fmaxf(m, v[q]); }
    __shared__ float red[8];
    __shared__ float red2[8];
    for (int o = 16; o >= 1; o >>= 1) m = fmaxf(m, __shfl_xor_sync(0xffffffffu, m, o));
    if ((tid & 31) == 0) red[tid >> 5] = m;
    __syncthreads();
    float mm = red[0];
    #pragma unroll
    for (int w = 1; w < 8; ++w) mm = fmaxf(mm, red[w]);
    float s = 0.f;
    #pragma unroll
    for (int q = 0; q < 4; ++q) { v[q] = expf(v[q] - mm); s += v[q]; }
    for (int o = 16; o >= 1; o >>= 1) s += __shfl_xor_sync(0xffffffffu, s, o);
    if ((tid & 31) == 0) red2[tid >> 5] = s;
    __syncthreads();
    float ss = 0.f;
    #pragma unroll
    for (int w = 0; w < 8; ++w) ss += red2[w];
    float inv = 1.f / ss;
    #pragma unroll
    for (int q = 0; q < 4; ++q) p[tid + q*256] = v[q] * inv;
}

// ---------------- attn_T = softmax(covT @ covT^T, axis=1) --------------------
__global__ void attnT_kernel(const float* __restrict__ tempE)
{
    __shared__ float cov[24][96];
    __shared__ float s[24][25];
    __shared__ float colmax[24], colsum[24];
    int b = blockIdx.x;
    int j = threadIdx.x, i = threadIdx.y;
    int tid = i*24 + j;
    for (int q = tid; q < 2304; q += 576) {
        int t = q / 96, f = q % 96;
        cov[t][f] = tempE[((b*TT + t)*NN)*FF + f];   // n = 0 slice
    }
    __syncthreads();
    float acc = 0.f;
    #pragma unroll
    for (int f = 0; f < 96; ++f) acc = fmaf(cov[i][f], cov[j][f], acc);
    s[i][j] = acc;
    __syncthreads();
    if (i == 0) {
        float m = -1e30f;
        for (int t = 0; t < 24; ++t) m = fmaxf(m, s[t][j]);
        colmax[j] = m;
    }
    __syncthreads();
    float e = expf(acc - colmax[j]);
    s[i][j] = e;
    __syncthreads();
    if (i == 0) {
        float sm0 = 0.f;
        for (int t = 0; t < 24; ++t) sm0 += s[t][j];
        colsum[j] = sm0;
    }
    __syncthreads();
    g_attnT[(b*TT + i)*TT + j] = e / colsum[j];
}

// ---------------- temporal branch v2: 288 threads, register-hoisted ----------
__global__ __launch_bounds__(288)
void temporal2(const float* __restrict__ input)
{
    __shared__ float hgs[2304];
    __shared__ float xts[2304];
    __shared__ float alph[2304];
    __shared__ float ats[576];
    __shared__ float elgs[96], ergs[96];
    int r = blockIdx.x;              // r = b*N + n
    int b = r >> 10, n = r & 1023;
    int tid = threadIdx.x;           // 288
    for (int q = tid; q < 2304; q += 288) hgs[q] = g_hg[(size_t)r*2304 + q];
    for (int q = tid; q < 2304; q += 288) {
        int t = q / 96, f = q % 96;
        xts[q] = input[((b*TT + t)*NN + n)*FF + f];
    }
    if (tid < 96) { elgs[tid] = g_elg[r*96 + tid]; ergs[tid] = g_erg[r*96 + tid]; }
    for (int q = tid; q < 576; q += 288) ats[q] = g_attnT[(n & 3)*576 + q]; // idx = r%B = n%4
    __syncthreads();
    if (tid < 96) {                  // softmax over j for (i,g)
        int i = tid >> 2, g = tid & 3;
        float eli = elgs[i*4 + g];
        float ev[24];
        float m = -1e30f;
        #pragma unroll
        for (int j = 0; j < 24; ++j) {
            float x = eli + ergs[j*4 + g];
            x = (x >= 0.f) ? x : 0.2f*x;
            ev[j] = x;
            m = fmaxf(m, x);
        }
        float s = 0.f;
        #pragma unroll
        for (int j = 0; j < 24; ++j) { ev[j] = expf(ev[j] - m); s += ev[j]; }
        float inv = 1.f / s;
        #pragma unroll
        for (int j = 0; j < 24; ++j) alph[tid*24 + j] = ev[j]*inv;
    }
    __syncthreads();

    int f = tid % 96, tr = tid / 96;       // tr 0..2
    int g = f / 24;
    float hv[24], xv[24];
    #pragma unroll
    for (int j = 0; j < 24; ++j) { hv[j] = hgs[j*96 + f]; xv[j] = xts[j*96 + f]; }
    #pragma unroll
    for (int s = 0; s < 8; ++s) {
        int i = tr + 3*s;
        float xa = 0.f, ea = 0.f;
        const float* ap = &alph[(i*4 + g)*24];
        const float* tp = &ats[i*24];
        #pragma unroll
        for (int j = 0; j < 24; ++j) {
            xa = fmaf(ap[j], hv[j], xa);
            ea = fmaf(tp[j], xv[j], ea);
        }
        float sg = 1.f / (1.f + expf(-ea));
        g_temporal[(size_t)((b*TT + i)*NN + n)*FF + f] = xv[i] + xa*sg;
    }
}

// ---------------- fusion (tensor-core): z = sigmoid([sp,tp]@Wf + bf) ---------
__global__ __launch_bounds__(256)
void fusion_tc(const float* __restrict__ input, const float* __restrict__ Wf,
               const float* __restrict__ bf, float* __restrict__ outp)
{
    extern __shared__ float sm[];
    float*    Xsp = sm;                                  // [128][100] fp32
    float*    Xtp = sm + 128*100;                        // [128][100] fp32
    uint32_t* Ws  = (uint32_t*)(sm + 2*128*100);         // [192][104] tf32

    const int tid = threadIdx.x;
    const int row0 = blockIdx.x * 128;

    for (int i = tid; i < 192*24; i += 256) {
        int k = i / 24, c4 = i % 24;
        float4 v = reinterpret_cast<const float4*>(Wf)[i];
        *reinterpret_cast<uint4*>(&Ws[k*104 + c4*4]) =
            make_uint4(f2tf32(v.x), f2tf32(v.y), f2tf32(v.z), f2tf32(v.w));
    }
    for (int i = tid; i < 3072; i += 256) {
        int r = i / 24, c4 = i % 24;
        size_t off = (size_t)(row0 + r)*96 + c4*4;
        *reinterpret_cast<float4*>(&Xsp[r*100 + c4*4]) = *reinterpret_cast<const float4*>(g_spatial + off);
        *reinterpret_cast<float4*>(&Xtp[r*100 + c4*4]) = *reinterpret_cast<const float4*>(g_temporal + off);
    }
    __syncthreads();

    const int lane = tid & 31, w = tid >> 5;
    const int g = lane >> 2, tig = lane & 3;
    const int r0 = w * 16;

    float acc[12][4];
    #pragma unroll
    for (int nt = 0; nt < 12; ++nt)
        #pragma unroll
        for (int q = 0; q < 4; ++q) acc[nt][q] = 0.f;

    #pragma unroll
    for (int ks = 0; ks < 12; ++ks) {           // spatial half (Wf rows 0..95)
        int k0 = ks * 8;
        uint32_t a[4];
        a[0] = f2tf32(Xsp[(r0+g  )*100 + k0 + tig    ]);
        a[1] = f2tf32(Xsp[(r0+g+8)*100 + k0 + tig    ]);
        a[2] = f2tf32(Xsp[(r0+g  )*100 + k0 + tig + 4]);
        a[3] = f2tf32(Xsp[(r0+g+8)*100 + k0 + tig + 4]);
        #pragma unroll
        for (int nt = 0; nt < 12; ++nt) {
            uint32_t b0 = Ws[(k0+tig  )*104 + nt*8 + g];
            uint32_t b1 = Ws[(k0+tig+4)*104 + nt*8 + g];
            mma_tf32(acc[nt], a, b0, b1);
        }
    }
    #pragma unroll
    for (int ks = 0; ks < 12; ++ks) {           // temporal half (Wf rows 96..191)
        int k0 = ks * 8;
        uint32_t a[4];
        a[0] = f2tf32(Xtp[(r0+g  )*100 + k0 + tig    ]);
        a[1] = f2tf32(Xtp[(r0+g+8)*100 + k0 + tig    ]);
        a[2] = f2tf32(Xtp[(r0+g  )*100 + k0 + tig + 4]);
        a[3] = f2tf32(Xtp[(r0+g+8)*100 + k0 + tig + 4]);
        #pragma unroll
        for (int nt = 0; nt < 12; ++nt) {
            uint32_t b0 = Ws[(96+k0+tig  )*104 + nt*8 + g];
            uint32_t b1 = Ws[(96+k0+tig+4)*104 + nt*8 + g];
            mma_tf32(acc[nt], a, b0, b1);
        }
    }

    const int gr0 = row0 + r0 + g, gr1 = gr0 + 8;
    const int rl0 = r0 + g, rl1 = rl0 + 8;
    #pragma unroll
    for (int nt = 0; nt < 12; ++nt) {
        int col = nt*8 + 2*tig;
        float b0v = bf[col], b1v = bf[col+1];
        float2 in0 = *reinterpret_cast<const float2*>(input + (size_t)gr0*96 + col);
        float2 in1 = *reinterpret_cast<const float2*>(input + (size_t)gr1*96 + col);
        float z00 = 1.f/(1.f+expf(-(acc[nt][0] + b0v)));
        float z01 = 1.f/(1.f+expf(-(acc[nt][1] + b1v)));
        float z10 = 1.f/(1.f+expf(-(acc[nt][2] + b0v)));
        float z11 = 1.f/(1.f+expf(-(acc[nt][3] + b1v)));
        float sp00 = Xsp[rl0*100 + col], sp01 = Xsp[rl0*100 + col + 1];
        float sp10 = Xsp[rl1*100 + col], sp11 = Xsp[rl1*100 + col + 1];
        float tp00 = Xtp[rl0*100 + col], tp01 = Xtp[rl0*100 + col + 1];
        float tp10 = Xtp[rl1*100 + col], tp11 = Xtp[rl1*100 + col + 1];
        float2 o0 = make_float2(z00*sp00 + (1.f-z00)*tp00 + in0.x,
                                z01*sp01 + (1.f-z01)*tp01 + in0.y);
        float2 o1 = make_float2(z10*sp10 + (1.f-z10)*tp10 + in1.x,
                                z11*sp11 + (1.f-z11)*tp11 + in1.y);
        *reinterpret_cast<float2*>(outp + (size_t)gr0*96 + col) = o0;
        *reinterpret_cast<float2*>(outp + (size_t)gr1*96 + col) = o1;
    }
}

extern "C" void kernel_launch(void* const* d_in, const int* in_sizes, int n_in,
                              void* d_out, int out_size)
{
    const float* input = (const float*)d_in[0];
    const float* spatE = (const float*)d_in[1];
    const float* tempE = (const float*)d_in[2];
    const int*   s0 = (const int*)d_in[3];
    const int*   s1 = (const int*)d_in[5];
    const int*   s2 = (const int*)d_in[7];
    const float* W_d = (const float*)d_in[9];
    const float* al_d = (const float*)d_in[10];
    const float* ar_d = (const float*)d_in[11];
    const float* b_d = (const float*)d_in[12];
    const float* W_m = (const float*)d_in[13];
    const float* al_m = (const float*)d_in[14];
    const float* ar_m = (const float*)d_in[15];
    const float* b_m = (const float*)d_in[16];
    const float* W_s = (const float*)d_in[17];
    const float* al_s = (const float*)d_in[18];
    const float* ar_s = (const float*)d_in[19];
    const float* b_s = (const float*)d_in[20];
    const float* Wg  = (const float*)d_in[21];
    const float* agl = (const float*)d_in[22];
    const float* agr = (const float*)d_in[23];
    const float* Wf  = (const float*)d_in[24];
    const float* bf  = (const float*)d_in[25];
    float* out   = (float*)d_out;
    float* attnS = out + (size_t)RR*96;   // out (B,T,N,F) then attn_S (B,N,N)

    const int SP_SMEM  = (128*100 + 3*96*104) * 4;         // 171,008 B
    const int TP_SMEM  = (128*100 + 96*104) * 4;           //  91,136 B
    const int FUS_SMEM = (2*128*100 + 192*104) * 4;        // 182,272 B
    const int ATS_SMEM = (2*64*97) * 4;                    //  49,664 B

    static cudaStream_t stB = 0, stC = 0;
    static cudaEvent_t evFork = 0, evB = 0, evC = 0;
    static int inited = 0;
    static int use_streams = 0;
    if (!inited) {
        cudaFuncSetAttribute(gemm_tc_sp, cudaFuncAttributeMaxDynamicSharedMemorySize, SP_SMEM);
        cudaFuncSetAttribute(gemm_tc_tp, cudaFuncAttributeMaxDynamicSharedMemorySize, TP_SMEM);
        cudaFuncSetAttribute(fusion_tc,  cudaFuncAttributeMaxDynamicSharedMemorySize, FUS_SMEM);
        cudaFuncSetAttribute(attnS_gemm, cudaFuncAttributeMaxDynamicSharedMemorySize, ATS_SMEM);
        // create side streams/events on the (uncaptured) first call; if anything
        // fails, fall back permanently to the sequential default-stream path.
        use_streams = 1;
        if (cudaStreamCreateWithFlags(&stB, cudaStreamNonBlocking) != cudaSuccess) use_streams = 0;
        if (use_streams && cudaStreamCreateWithFlags(&stC, cudaStreamNonBlocking) != cudaSuccess) use_streams = 0;
        if (use_streams && cudaEventCreateWithFlags(&evFork, cudaEventDisableTiming) != cudaSuccess) use_streams = 0;
        if (use_streams && cudaEventCreateWithFlags(&evB,    cudaEventDisableTiming) != cudaSuccess) use_streams = 0;
        if (use_streams && cudaEventCreateWithFlags(&evC,    cudaEventDisableTiming) != cudaSuccess) use_streams = 0;
        inited = 1;
    }

    if (use_streams) {
        // Relax capture-mode strictness for cross-stream fork/join under capture.
        cudaStreamCaptureMode mode = cudaStreamCaptureModeRelaxed;
        cudaThreadExchangeStreamCaptureMode(&mode);

        cudaEventRecord(evFork, 0);
        cudaStreamWaitEvent(stB, evFork, 0);
        cudaStreamWaitEvent(stC, evFork, 0);

        // chain B: temporal projection -> attn_T -> temporal branch
        gemm_tc_tp<<<RGRID, 256, TP_SMEM, stB>>>(input, Wg, agl, agr);
        attnT_kernel<<<4, dim3(24,24), 0, stB>>>(tempE);
        temporal2<<<4096, 288, 0, stB>>>(input);
        cudaEventRecord(evB, stB);

        // chain C: attn_S output (independent)
        attnS_gemm<<<dim3(16,16,4), 256, ATS_SMEM, stC>>>(spatE, attnS);
        rowsoftmax1024<<<4096, 256, 0, stC>>>(attnS);
        cudaEventRecord(evC, stC);

        // chain A: spatial GEMM (3 gats) -> aggregation
        gemm_tc_sp<<<RGRID, 256, SP_SMEM>>>(input, spatE,
            W_d, W_m, W_s, al_d, al_m, al_s, ar_d, ar_m, ar_s);
        gat_agg2<<<dim3(NN, 3), 256>>>(s0, s1, s2, b_d, b_m, b_s, input);

        cudaStreamWaitEvent(0, evB, 0);
        fusion_tc<<<RGRID, 256, FUS_SMEM>>>(input, Wf, bf, out);
        cudaStreamWaitEvent(0, evC, 0);

        cudaThreadExchangeStreamCaptureMode(&mode);   // restore
    } else {
        // sequential fallback (identical to the R9-passing configuration)
        gemm_tc_sp<<<RGRID, 256, SP_SMEM>>>(input, spatE,
            W_d, W_m, W_s, al_d, al_m, al_s, ar_d, ar_m, ar_s);
        gemm_tc_tp<<<RGRID, 256, TP_SMEM>>>(input, Wg, agl, agr);
        gat_agg2<<<dim3(NN, 3), 256>>>(s0, s1, s2, b_d, b_m, b_s, input);
        attnS_gemm<<<dim3(16,16,4), 256, ATS_SMEM>>>(spatE, attnS);
        rowsoftmax1024<<<4096, 256>>>(attnS);
        attnT_kernel<<<4, dim3(24,24)>>>(tempE);
        temporal2<<<4096, 288>>>(input);
        fusion_tc<<<RGRID, 256, FUS_SMEM>>>(input, Wf, bf, out);
    }
}